// round 12
// baseline (speedup 1.0000x reference)
#include <cuda_runtime.h>
#include <cuda_fp16.h>
#include <math.h>
#include <stdint.h>

#define T_STEPS 512
#define BATCH   32
#define D_DIM   1024
#define N_DIM   1024
#define R_DIM   8
#define M_ROWS  (T_STEPS*BATCH)   /* 16384 */
#define EPSV    1e-6f
#define KC      64
#define STAGE   32768             /* A-part @0 (16K), B-part @16K */

// ---------------- scratch (static device arrays; no cudaMalloc) ------------
__device__ float g_v[M_ROWS * N_DIM];
__device__ float g_coef[M_ROWS * 24];
__device__ float g_nsq[M_ROWS];
__device__ float g_M[384 * 2048];
__device__ __half g_xh[M_ROWS * D_DIM];
__device__ __half g_wk[D_DIM * D_DIM];
__device__ __half g_wv[D_DIM * D_DIM];

// ---------------- transcendentals -------------------------------------------
__device__ __forceinline__ float out_silu(float s) {
    float xs = fminf(30.f, fmaxf(-30.f, s));
    float e  = __expf(-xs);
    return s * s * __fdividef(1.f, 1.f + e);
}
__device__ __forceinline__ float rcp_approx(float x) {
    float r;
    asm("rcp.approx.f32 %0, %1;" : "=f"(r) : "f"(x));
    return r;
}

// ---------------- PTX helpers ------------------------------------------------
__device__ __forceinline__ uint32_t smem_u32(const void* p) {
    uint32_t a;
    asm("{ .reg .u64 t; cvta.to.shared.u64 t, %1; cvt.u32.u64 %0, t; }"
        : "=r"(a) : "l"(p));
    return a;
}
__device__ __forceinline__ void cp16(uint32_t s, const void* g) {
    asm volatile("cp.async.cg.shared.global [%0], [%1], 16;"
                 :: "r"(s), "l"(g) : "memory");
}
#define LDSM_X4(r0, r1, r2, r3, addr) \
    asm volatile("ldmatrix.sync.aligned.m8n8.x4.shared.b16 {%0,%1,%2,%3}, [%4];" \
        : "=r"(r0), "=r"(r1), "=r"(r2), "=r"(r3) : "r"(addr))
#define MMA_F16(d, a, b0, b1) \
    asm volatile("mma.sync.aligned.m16n8k16.row.col.f32.f16.f16.f32 " \
        "{%0,%1,%2,%3},{%4,%5,%6,%7},{%8,%9},{%0,%1,%2,%3};" \
        : "+f"((d)[0]), "+f"((d)[1]), "+f"((d)[2]), "+f"((d)[3]) \
        : "r"((a)[0]), "r"((a)[1]), "r"((a)[2]), "r"((a)[3]), "r"(b0), "r"(b1))

// ============================================================================
// Convert: x -> fp16, Wk -> fp16, Wv -> fp16; zero g_nsq
// ============================================================================
__global__ __launch_bounds__(256) void convert_kernel(
    const float* __restrict__ x, const float* __restrict__ Wk,
    const float* __restrict__ Wv)
{
    int bid = blockIdx.x;
    const float* src;
    __half* dst;
    size_t idx;
    if (bid < 16384) {
        src = x; dst = g_xh; idx = (size_t)bid * 256 + threadIdx.x;
    } else if (bid < 17408) {
        src = Wk; dst = g_wk; idx = (size_t)(bid - 16384) * 256 + threadIdx.x;
    } else if (bid < 18432) {
        src = Wv; dst = g_wv; idx = (size_t)(bid - 17408) * 256 + threadIdx.x;
    } else {
        size_t z = (size_t)(bid - 18432) * 256 + threadIdx.x;
        ((float4*)g_nsq)[z] = make_float4(0.f, 0.f, 0.f, 0.f);
        return;
    }
    float4 v = ((const float4*)src)[idx];
    ((__half2*)dst)[idx*2]   = __half2{__float2half_rn(v.x), __float2half_rn(v.y)};
    ((__half2*)dst)[idx*2+1] = __half2{__float2half_rn(v.z), __float2half_rn(v.w)};
}

// ============================================================================
// Prep (plain fp32): g_M[p][d] = sum_n P[p][n]*Wk[n][d]; [.][1024+d] for Wq.
// ============================================================================
__global__ __launch_bounds__(128) void prep_kernel(
    const float* __restrict__ V0, const float* __restrict__ Wk,
    const float* __restrict__ Wq, const float* __restrict__ Wkr)
{
    __shared__ float sP[8][128];
    const int dx  = blockIdx.x;
    const int py  = blockIdx.y;
    const int tid = threadIdx.x;
    const float* W = (dx < 8) ? Wk : Wq;
    const int d = (dx & 7) * 128 + tid;

    float acc[8];
#pragma unroll
    for (int j = 0; j < 8; j++) acc[j] = 0.f;

    for (int n0 = 0; n0 < N_DIM; n0 += 128) {
        __syncthreads();
        for (int idx = tid; idx < 1024; idx += 128) {
            int j = idx >> 7, n = idx & 127;
            float v;
            if (py < 32) v = V0[((size_t)py * N_DIM + n0 + n) * 8 + j];
            else         v = Wkr[(size_t)j * N_DIM + n0 + n];
            sP[j][n] = v;
        }
        __syncthreads();
#pragma unroll 4
        for (int n = 0; n < 128; n++) {
            float w = W[(size_t)(n0 + n) * D_DIM + d];
#pragma unroll
            for (int j = 0; j < 8; j++) acc[j] = fmaf(sP[j][n], w, acc[j]);
        }
    }

    const int prow = py * 8;
    const int dcol = ((dx < 8) ? 0 : 1024) + (dx & 7) * 128 + tid;
#pragma unroll
    for (int j = 0; j < 8; j++)
        g_M[(size_t)(prow + j) * 2048 + dcol] = acc[j];
}

// ============================================================================
// Single-product fp16 HMMA GEMM, 16 K-chunks, 3-stage pipeline (96KB),
// 2 CTAs/SM. MODE 0: xh*Wv -> g_v. MODE 1: xh*Wk -> row SSQ -> g_nsq.
// ============================================================================
template<int MODE>
__device__ __forceinline__ void fill_vstage(uint32_t st, int chunk, int tid,
                                            int mt, int nt)
{
    const __half* A = g_xh + (size_t)mt * 128 * D_DIM + chunk * KC;
    const __half* B = ((MODE == 0) ? g_wv : g_wk)
                    + (size_t)nt * 128 * D_DIM + chunk * KC;
#pragma unroll
    for (int v = tid; v < 1024; v += 256) {
        int row = v >> 3, c = v & 7;
        uint32_t so = (uint32_t)(row * 128 + ((c * 16) ^ ((row & 7) << 4)));
        size_t go = (size_t)row * D_DIM + c * 8;
        cp16(st + so,         A + go);
        cp16(st + 16384 + so, B + go);
    }
}

template<int MODE>
__global__ __launch_bounds__(256, 2) void gemm_virtual()
{
    constexpr int NCHUNK = 16;
    extern __shared__ char smem[];
    const uint32_t sb = smem_u32(smem);
    const int tid  = threadIdx.x;
    const int lane = tid & 31, wid = tid >> 5;
    const int wm = wid >> 1, wn = wid & 1;
    const int nt = blockIdx.x, mt = blockIdx.y;

    const uint32_t aRowOff = (uint32_t)((wm * 32 + (lane & 15)) * 128);
    const uint32_t aSeg    = (uint32_t)((lane >> 4) * 16);
    const uint32_t bRowOff = (uint32_t)((wn * 64 + ((lane >> 4) << 3) + (lane & 7)) * 128);
    const uint32_t bSeg    = (uint32_t)(((lane >> 3) & 1) * 16);
    const uint32_t xorm    = (uint32_t)((lane & 7) << 4);

    float acc[2][8][4];
#pragma unroll
    for (int i = 0; i < 2; i++)
#pragma unroll
        for (int j = 0; j < 8; j++)
#pragma unroll
            for (int e = 0; e < 4; e++) acc[i][j][e] = 0.f;

    fill_vstage<MODE>(sb, 0, tid, mt, nt);
    asm volatile("cp.async.commit_group;" ::: "memory");
    fill_vstage<MODE>(sb + STAGE, 1, tid, mt, nt);
    asm volatile("cp.async.commit_group;" ::: "memory");

    for (int c = 0; c < NCHUNK; c++) {
        if (c + 2 < NCHUNK) {
            fill_vstage<MODE>(sb + ((c + 2) % 3) * STAGE, c + 2, tid, mt, nt);
            asm volatile("cp.async.commit_group;" ::: "memory");
            asm volatile("cp.async.wait_group 2;" ::: "memory");
        } else if (c + 1 < NCHUNK) {
            asm volatile("cp.async.wait_group 1;" ::: "memory");
        } else {
            asm volatile("cp.async.wait_group 0;" ::: "memory");
        }
        __syncthreads();

        const uint32_t sA = sb + (c % 3) * STAGE;
        const uint32_t sB = sA + 16384;

#pragma unroll
        for (int ks = 0; ks < 4; ks++) {
            const uint32_t kb = (uint32_t)(ks * 32);
            uint32_t a[2][4];
#pragma unroll
            for (int i = 0; i < 2; i++) {
                uint32_t ad = sA + i * 2048 + aRowOff + ((kb + aSeg) ^ xorm);
                LDSM_X4(a[i][0], a[i][1], a[i][2], a[i][3], ad);
            }
#pragma unroll
            for (int jp = 0; jp < 4; jp++) {
                uint32_t b0, b1, b2, b3;
                uint32_t bd = sB + jp * 2048 + bRowOff + ((kb + bSeg) ^ xorm);
                LDSM_X4(b0, b1, b2, b3, bd);
#pragma unroll
                for (int i = 0; i < 2; i++) {
                    MMA_F16(acc[i][2*jp],     a[i], b0, b1);
                    MMA_F16(acc[i][2*jp + 1], a[i], b2, b3);
                }
            }
        }
        __syncthreads();
    }

    if (MODE == 0) {
#pragma unroll
        for (int i = 0; i < 2; i++) {
            const int r0 = mt * 128 + wm * 32 + i * 16 + (lane >> 2);
#pragma unroll
            for (int j = 0; j < 8; j++) {
                const int col = nt * 128 + wn * 64 + j * 8 + (lane & 3) * 2;
                *(float2*)&g_v[(size_t)r0 * N_DIM + col] =
                    make_float2(acc[i][j][0], acc[i][j][1]);
                *(float2*)&g_v[(size_t)(r0 + 8) * N_DIM + col] =
                    make_float2(acc[i][j][2], acc[i][j][3]);
            }
        }
    } else {
#pragma unroll
        for (int i = 0; i < 2; i++) {
            float s0 = 0.f, s1 = 0.f;
#pragma unroll
            for (int j = 0; j < 8; j++) {
                s0 = fmaf(acc[i][j][0], acc[i][j][0], s0);
                s0 = fmaf(acc[i][j][1], acc[i][j][1], s0);
                s1 = fmaf(acc[i][j][2], acc[i][j][2], s1);
                s1 = fmaf(acc[i][j][3], acc[i][j][3], s1);
            }
            s0 += __shfl_xor_sync(0xffffffffu, s0, 1);
            s0 += __shfl_xor_sync(0xffffffffu, s0, 2);
            s1 += __shfl_xor_sync(0xffffffffu, s1, 1);
            s1 += __shfl_xor_sync(0xffffffffu, s1, 2);
            const int r0 = mt * 128 + wm * 32 + i * 16 + (lane >> 2);
            if ((lane & 3) == 0) {
                atomicAdd(&g_nsq[r0],     s0);
                atomicAdd(&g_nsq[r0 + 8], s1);
            }
        }
    }
}

// ============================================================================
// Coef: per (t,b), 24 raw dots of x against fused M rows (Vtk | kr | Vtq)
// ============================================================================
__global__ __launch_bounds__(256) void coef_kernel(const float* __restrict__ x)
{
    __shared__ float sred[8 * 24];

    const int b  = blockIdx.y;
    const int t0 = blockIdx.x * 16;
    const int tid = threadIdx.x;
    const int lane = tid & 31, warp = tid >> 5;

    float Mk[4][8], Mr[4][8], Mq[4][8];
#pragma unroll
    for (int ii = 0; ii < 4; ii++) {
        int d = tid + ii * 256;
#pragma unroll
        for (int j = 0; j < 8; j++) {
            Mk[ii][j] = g_M[(size_t)(b * 8 + j) * 2048 + d];
            Mq[ii][j] = g_M[(size_t)(b * 8 + j) * 2048 + 1024 + d];
            Mr[ii][j] = g_M[(size_t)(256 + j) * 2048 + d];
        }
    }

    for (int tt = 0; tt < 16; tt++) {
        const int t = t0 + tt;
        const float* xrow = &x[(size_t)(t * BATCH + b) * D_DIM];

        float acc[24];
#pragma unroll
        for (int c = 0; c < 24; c++) acc[c] = 0.f;

#pragma unroll
        for (int ii = 0; ii < 4; ii++) {
            float xv = xrow[tid + ii * 256];
#pragma unroll
            for (int j = 0; j < 8; j++) {
                acc[j]      = fmaf(Mk[ii][j], xv, acc[j]);
                acc[8 + j]  = fmaf(Mr[ii][j], xv, acc[8 + j]);
                acc[16 + j] = fmaf(Mq[ii][j], xv, acc[16 + j]);
            }
        }
#pragma unroll
        for (int off = 16; off > 0; off >>= 1)
#pragma unroll
            for (int c = 0; c < 24; c++)
                acc[c] += __shfl_down_sync(0xffffffffu, acc[c], off);

        if (lane == 0) {
#pragma unroll
            for (int c = 0; c < 24; c++) sred[warp * 24 + c] = acc[c];
        }
        __syncthreads();
        if (tid < 24) {
            float s = 0.f;
#pragma unroll
            for (int w = 0; w < 8; w++) s += sred[w * 24 + tid];
            g_coef[(size_t)(t * BATCH + b) * 24 + tid] = s;
        }
        __syncthreads();
    }
}

// ============================================================================
// Scan: 128-thread blocks, 2 threads per row; tanh = 1 - 2/(e^{2x}+1)
// (single upper clamp), 4-way batched rcp.
// ============================================================================
__global__ __launch_bounds__(128) void scan_kernel(
    const float* __restrict__ U0, float* __restrict__ out, int writeExtra)
{
    const int CH = 64;
    __shared__ float sc[CH * 24];
    __shared__ float ssc[CH];

    const int b    = blockIdx.y;
    const int tid  = threadIdx.x;
    const int lane = tid & 31, warp = tid >> 5;
    const int h    = lane >> 4;
    const int h4   = h * 4;
    const int i    = blockIdx.x * 64 + warp * 16 + (lane & 15);

    float U[4];
    {
        float4 u = *(const float4*)&U0[((size_t)b * N_DIM + i) * 8 + h4];
        U[0] = u.x; U[1] = u.y; U[2] = u.z; U[3] = u.w;
    }

    float vcur = g_v[(size_t)b * N_DIM + i];

    for (int tc = 0; tc < T_STEPS; tc += CH) {
        __syncthreads();
        if (tid < CH) {
            float ns = g_nsq[(size_t)(tc + tid) * BATCH + b];
            ssc[tid] = __fdividef(1.f, sqrtf(ns) + EPSV);
        }
        for (int idx = tid; idx < CH * 24; idx += 128) {
            int tt = idx / 24;
            sc[idx] = g_coef[(size_t)((tc + tt) * BATCH + b) * 24 + (idx - tt * 24)];
        }
        __syncthreads();

#pragma unroll 2
        for (int tt = 0; tt < CH; tt++) {
            const int t = tc + tt;
            float vnext = (t + 1 < T_STEPS)
                        ? g_v[(size_t)((t + 1) * BATCH + b) * N_DIM + i] : 0.f;
            const float* c = &sc[tt * 24];
            const float s = ssc[tt];

            float part = U[0] * c[h4];
#pragma unroll
            for (int j = 1; j < 4; j++) part = fmaf(U[j], c[h4 + j], part);
            float ret = (part + __shfl_xor_sync(0xffffffffu, part, 16)) * s;
            float dls = (vcur - ret) * s;

            // tanh(x) = 1 - 2/(e^{2x}+1); upper clamp keeps 4-product finite.
            float d[4];
#pragma unroll
            for (int j = 0; j < 4; j++) {
                float xx = fmaf(dls, c[8 + h4 + j], U[j]);
                xx = fminf(9.f, xx);
                d[j] = __expf(xx + xx) + 1.f;
            }
            float p01 = d[0] * d[1], p23 = d[2] * d[3];
            float r = rcp_approx(p01 * p23);
            float i01 = r * p23, i23 = r * p01;
            U[0] = fmaf(-2.f, i01 * d[1], 1.f);
            U[1] = fmaf(-2.f, i01 * d[0], 1.f);
            U[2] = fmaf(-2.f, i23 * d[3], 1.f);
            U[3] = fmaf(-2.f, i23 * d[2], 1.f);

            float p2 = U[0] * c[16 + h4];
#pragma unroll
            for (int j = 1; j < 4; j++) p2 = fmaf(U[j], c[16 + h4 + j], p2);
            float sq = p2 + __shfl_xor_sync(0xffffffffu, p2, 16);

            if (h == 0)
                out[(size_t)(t * BATCH + b) * N_DIM + i] = out_silu(sq);
            vcur = vnext;
        }
    }

    if (writeExtra) {
        float* uf = out + (size_t)M_ROWS * N_DIM + ((size_t)b * N_DIM + i) * 8 + h4;
        *(float4*)uf = make_float4(U[0], U[1], U[2], U[3]);
    }
}

// ============================================================================
struct AuxStreams {
    cudaStream_t s2;
    cudaEvent_t  fork, conv, join;
    AuxStreams() {
        cudaStreamCreate(&s2);
        cudaEventCreateWithFlags(&fork, cudaEventDisableTiming);
        cudaEventCreateWithFlags(&conv, cudaEventDisableTiming);
        cudaEventCreateWithFlags(&join, cudaEventDisableTiming);
    }
};

extern "C" void kernel_launch(void* const* d_in, const int* in_sizes, int n_in,
                              void* d_out, int out_size)
{
    const float* x   = (const float*)d_in[0];
    const float* Wk  = (const float*)d_in[1];
    const float* Wv  = (const float*)d_in[2];
    const float* Wq  = (const float*)d_in[3];
    const float* Wkr = (const float*)d_in[4];
    const float* U0  = (const float*)d_in[5];
    const float* V0  = (const float*)d_in[6];
    float* out = (float*)d_out;

    (void)in_sizes; (void)n_in;

    static AuxStreams aux;

    cudaFuncSetAttribute(gemm_virtual<0>,
                         cudaFuncAttributeMaxDynamicSharedMemorySize, 3 * STAGE);
    cudaFuncSetAttribute(gemm_virtual<1>,
                         cudaFuncAttributeMaxDynamicSharedMemorySize, 3 * STAGE);

    // Chain B (s2): prep -> coef; then norm-GEMM after convert completes.
    cudaEventRecord(aux.fork, 0);
    cudaStreamWaitEvent(aux.s2, aux.fork, 0);
    prep_kernel<<<dim3(16, 33), 128, 0, aux.s2>>>(V0, Wk, Wq, Wkr);
    coef_kernel<<<dim3(T_STEPS / 16, BATCH), 256, 0, aux.s2>>>(x);

    // Chain A (stream 0): convert -> v-GEMM (fp16, 1 product)
    convert_kernel<<<18448, 256>>>(x, Wk, Wv);
    cudaEventRecord(aux.conv, 0);
    gemm_virtual<0><<<dim3(8, 128), 256, 3 * STAGE>>>();

    // norm-GEMM (fp16, 1 product) on s2, co-scheduled with v-GEMM
    cudaStreamWaitEvent(aux.s2, aux.conv, 0);
    gemm_virtual<1><<<dim3(8, 128), 256, 3 * STAGE, aux.s2>>>();
    cudaEventRecord(aux.join, aux.s2);

    // Join, then scan
    cudaStreamWaitEvent(0, aux.join, 0);
    const int extraElems = 2 * BATCH * N_DIM * R_DIM;
    int writeExtra = (out_size >= M_ROWS * N_DIM + extraElems) ? 1 : 0;
    scan_kernel<<<dim3(N_DIM / 64, BATCH), 128>>>(U0, out, writeExtra);

    if (writeExtra) {
        cudaMemcpyAsync(out + (size_t)M_ROWS * N_DIM + BATCH * N_DIM * R_DIM,
                        V0, (size_t)BATCH * N_DIM * R_DIM * sizeof(float),
                        cudaMemcpyDeviceToDevice, 0);
    }
}

// round 13
// speedup vs baseline: 1.3979x; 1.3979x over previous
#include <cuda_runtime.h>
#include <cuda_fp16.h>
#include <math.h>
#include <stdint.h>

#define T_STEPS 512
#define BATCH   32
#define D_DIM   1024
#define N_DIM   1024
#define R_DIM   8
#define M_ROWS  (T_STEPS*BATCH)   /* 16384 */
#define EPSV    1e-6f
#define KC      64
#define STAGE   32768             /* A-part @0 (16K), B-part @16K */

// ---------------- scratch (static device arrays; no cudaMalloc) ------------
__device__ float g_v[M_ROWS * N_DIM];
__device__ float g_coef[M_ROWS * 24];
__device__ float g_nsq[M_ROWS];
__device__ float g_M[384 * 2048];
__device__ __half g_xh[M_ROWS * D_DIM];
__device__ __half g_wk[D_DIM * D_DIM];
__device__ __half g_wv[D_DIM * D_DIM];

// ---------------- transcendentals -------------------------------------------
__device__ __forceinline__ float out_silu(float s) {
    float xs = fminf(30.f, fmaxf(-30.f, s));
    float e  = __expf(-xs);
    return s * s * __fdividef(1.f, 1.f + e);
}
__device__ __forceinline__ float rcp_approx(float x) {
    float r;
    asm("rcp.approx.f32 %0, %1;" : "=f"(r) : "f"(x));
    return r;
}

// ---------------- PTX helpers ------------------------------------------------
__device__ __forceinline__ uint32_t smem_u32(const void* p) {
    uint32_t a;
    asm("{ .reg .u64 t; cvta.to.shared.u64 t, %1; cvt.u32.u64 %0, t; }"
        : "=r"(a) : "l"(p));
    return a;
}
__device__ __forceinline__ void cp16(uint32_t s, const void* g) {
    asm volatile("cp.async.cg.shared.global [%0], [%1], 16;"
                 :: "r"(s), "l"(g) : "memory");
}
#define LDSM_X4(r0, r1, r2, r3, addr) \
    asm volatile("ldmatrix.sync.aligned.m8n8.x4.shared.b16 {%0,%1,%2,%3}, [%4];" \
        : "=r"(r0), "=r"(r1), "=r"(r2), "=r"(r3) : "r"(addr))
#define MMA_F16(d, a, b0, b1) \
    asm volatile("mma.sync.aligned.m16n8k16.row.col.f32.f16.f16.f32 " \
        "{%0,%1,%2,%3},{%4,%5,%6,%7},{%8,%9},{%0,%1,%2,%3};" \
        : "+f"((d)[0]), "+f"((d)[1]), "+f"((d)[2]), "+f"((d)[3]) \
        : "r"((a)[0]), "r"((a)[1]), "r"((a)[2]), "r"((a)[3]), "r"(b0), "r"(b1))

// ============================================================================
// Convert: x -> fp16, Wk -> fp16, Wv -> fp16; zero g_nsq
// ============================================================================
__global__ __launch_bounds__(256) void convert_kernel(
    const float* __restrict__ x, const float* __restrict__ Wk,
    const float* __restrict__ Wv)
{
    int bid = blockIdx.x;
    const float* src;
    __half* dst;
    size_t idx;
    if (bid < 16384) {
        src = x; dst = g_xh; idx = (size_t)bid * 256 + threadIdx.x;
    } else if (bid < 17408) {
        src = Wk; dst = g_wk; idx = (size_t)(bid - 16384) * 256 + threadIdx.x;
    } else if (bid < 18432) {
        src = Wv; dst = g_wv; idx = (size_t)(bid - 17408) * 256 + threadIdx.x;
    } else {
        size_t z = (size_t)(bid - 18432) * 256 + threadIdx.x;
        ((float4*)g_nsq)[z] = make_float4(0.f, 0.f, 0.f, 0.f);
        return;
    }
    float4 v = ((const float4*)src)[idx];
    ((__half2*)dst)[idx*2]   = __half2{__float2half_rn(v.x), __float2half_rn(v.y)};
    ((__half2*)dst)[idx*2+1] = __half2{__float2half_rn(v.z), __float2half_rn(v.w)};
}

// ============================================================================
// Prep (plain fp32): g_M[p][d] = sum_n P[p][n]*Wk[n][d]; [.][1024+d] for Wq.
// ============================================================================
__global__ __launch_bounds__(128) void prep_kernel(
    const float* __restrict__ V0, const float* __restrict__ Wk,
    const float* __restrict__ Wq, const float* __restrict__ Wkr)
{
    __shared__ float sP[8][128];
    const int dx  = blockIdx.x;
    const int py  = blockIdx.y;
    const int tid = threadIdx.x;
    const float* W = (dx < 8) ? Wk : Wq;
    const int d = (dx & 7) * 128 + tid;

    float acc[8];
#pragma unroll
    for (int j = 0; j < 8; j++) acc[j] = 0.f;

    for (int n0 = 0; n0 < N_DIM; n0 += 128) {
        __syncthreads();
        for (int idx = tid; idx < 1024; idx += 128) {
            int j = idx >> 7, n = idx & 127;
            float v;
            if (py < 32) v = V0[((size_t)py * N_DIM + n0 + n) * 8 + j];
            else         v = Wkr[(size_t)j * N_DIM + n0 + n];
            sP[j][n] = v;
        }
        __syncthreads();
#pragma unroll 4
        for (int n = 0; n < 128; n++) {
            float w = W[(size_t)(n0 + n) * D_DIM + d];
#pragma unroll
            for (int j = 0; j < 8; j++) acc[j] = fmaf(sP[j][n], w, acc[j]);
        }
    }

    const int prow = py * 8;
    const int dcol = ((dx < 8) ? 0 : 1024) + (dx & 7) * 128 + tid;
#pragma unroll
    for (int j = 0; j < 8; j++)
        g_M[(size_t)(prow + j) * 2048 + dcol] = acc[j];
}

// ============================================================================
// Single-product fp16 HMMA GEMM, 16 K-chunks, 3-stage pipeline (96KB),
// 2 CTAs/SM. MODE 0: xh*Wv -> g_v. MODE 1: xh*Wk -> row SSQ -> g_nsq.
// ============================================================================
template<int MODE>
__device__ __forceinline__ void fill_vstage(uint32_t st, int chunk, int tid,
                                            int mt, int nt)
{
    const __half* A = g_xh + (size_t)mt * 128 * D_DIM + chunk * KC;
    const __half* B = ((MODE == 0) ? g_wv : g_wk)
                    + (size_t)nt * 128 * D_DIM + chunk * KC;
#pragma unroll
    for (int v = tid; v < 1024; v += 256) {
        int row = v >> 3, c = v & 7;
        uint32_t so = (uint32_t)(row * 128 + ((c * 16) ^ ((row & 7) << 4)));
        size_t go = (size_t)row * D_DIM + c * 8;
        cp16(st + so,         A + go);
        cp16(st + 16384 + so, B + go);
    }
}

template<int MODE>
__global__ __launch_bounds__(256, 2) void gemm_virtual()
{
    constexpr int NCHUNK = 16;
    extern __shared__ char smem[];
    const uint32_t sb = smem_u32(smem);
    const int tid  = threadIdx.x;
    const int lane = tid & 31, wid = tid >> 5;
    const int wm = wid >> 1, wn = wid & 1;
    const int nt = blockIdx.x, mt = blockIdx.y;

    const uint32_t aRowOff = (uint32_t)((wm * 32 + (lane & 15)) * 128);
    const uint32_t aSeg    = (uint32_t)((lane >> 4) * 16);
    const uint32_t bRowOff = (uint32_t)((wn * 64 + ((lane >> 4) << 3) + (lane & 7)) * 128);
    const uint32_t bSeg    = (uint32_t)(((lane >> 3) & 1) * 16);
    const uint32_t xorm    = (uint32_t)((lane & 7) << 4);

    float acc[2][8][4];
#pragma unroll
    for (int i = 0; i < 2; i++)
#pragma unroll
        for (int j = 0; j < 8; j++)
#pragma unroll
            for (int e = 0; e < 4; e++) acc[i][j][e] = 0.f;

    fill_vstage<MODE>(sb, 0, tid, mt, nt);
    asm volatile("cp.async.commit_group;" ::: "memory");
    fill_vstage<MODE>(sb + STAGE, 1, tid, mt, nt);
    asm volatile("cp.async.commit_group;" ::: "memory");

    for (int c = 0; c < NCHUNK; c++) {
        if (c + 2 < NCHUNK) {
            fill_vstage<MODE>(sb + ((c + 2) % 3) * STAGE, c + 2, tid, mt, nt);
            asm volatile("cp.async.commit_group;" ::: "memory");
            asm volatile("cp.async.wait_group 2;" ::: "memory");
        } else if (c + 1 < NCHUNK) {
            asm volatile("cp.async.wait_group 1;" ::: "memory");
        } else {
            asm volatile("cp.async.wait_group 0;" ::: "memory");
        }
        __syncthreads();

        const uint32_t sA = sb + (c % 3) * STAGE;
        const uint32_t sB = sA + 16384;

#pragma unroll
        for (int ks = 0; ks < 4; ks++) {
            const uint32_t kb = (uint32_t)(ks * 32);
            uint32_t a[2][4];
#pragma unroll
            for (int i = 0; i < 2; i++) {
                uint32_t ad = sA + i * 2048 + aRowOff + ((kb + aSeg) ^ xorm);
                LDSM_X4(a[i][0], a[i][1], a[i][2], a[i][3], ad);
            }
#pragma unroll
            for (int jp = 0; jp < 4; jp++) {
                uint32_t b0, b1, b2, b3;
                uint32_t bd = sB + jp * 2048 + bRowOff + ((kb + bSeg) ^ xorm);
                LDSM_X4(b0, b1, b2, b3, bd);
#pragma unroll
                for (int i = 0; i < 2; i++) {
                    MMA_F16(acc[i][2*jp],     a[i], b0, b1);
                    MMA_F16(acc[i][2*jp + 1], a[i], b2, b3);
                }
            }
        }
        __syncthreads();
    }

    if (MODE == 0) {
#pragma unroll
        for (int i = 0; i < 2; i++) {
            const int r0 = mt * 128 + wm * 32 + i * 16 + (lane >> 2);
#pragma unroll
            for (int j = 0; j < 8; j++) {
                const int col = nt * 128 + wn * 64 + j * 8 + (lane & 3) * 2;
                *(float2*)&g_v[(size_t)r0 * N_DIM + col] =
                    make_float2(acc[i][j][0], acc[i][j][1]);
                *(float2*)&g_v[(size_t)(r0 + 8) * N_DIM + col] =
                    make_float2(acc[i][j][2], acc[i][j][3]);
            }
        }
    } else {
#pragma unroll
        for (int i = 0; i < 2; i++) {
            float s0 = 0.f, s1 = 0.f;
#pragma unroll
            for (int j = 0; j < 8; j++) {
                s0 = fmaf(acc[i][j][0], acc[i][j][0], s0);
                s0 = fmaf(acc[i][j][1], acc[i][j][1], s0);
                s1 = fmaf(acc[i][j][2], acc[i][j][2], s1);
                s1 = fmaf(acc[i][j][3], acc[i][j][3], s1);
            }
            s0 += __shfl_xor_sync(0xffffffffu, s0, 1);
            s0 += __shfl_xor_sync(0xffffffffu, s0, 2);
            s1 += __shfl_xor_sync(0xffffffffu, s1, 1);
            s1 += __shfl_xor_sync(0xffffffffu, s1, 2);
            const int r0 = mt * 128 + wm * 32 + i * 16 + (lane >> 2);
            if ((lane & 3) == 0) {
                atomicAdd(&g_nsq[r0],     s0);
                atomicAdd(&g_nsq[r0 + 8], s1);
            }
        }
    }
}

// ============================================================================
// Coef: per (t,b), 24 raw dots of x against fused M rows (Vtk | kr | Vtq)
// ============================================================================
__global__ __launch_bounds__(256) void coef_kernel(const float* __restrict__ x)
{
    __shared__ float sred[8 * 24];

    const int b  = blockIdx.y;
    const int t0 = blockIdx.x * 16;
    const int tid = threadIdx.x;
    const int lane = tid & 31, warp = tid >> 5;

    float Mk[4][8], Mr[4][8], Mq[4][8];
#pragma unroll
    for (int ii = 0; ii < 4; ii++) {
        int d = tid + ii * 256;
#pragma unroll
        for (int j = 0; j < 8; j++) {
            Mk[ii][j] = g_M[(size_t)(b * 8 + j) * 2048 + d];
            Mq[ii][j] = g_M[(size_t)(b * 8 + j) * 2048 + 1024 + d];
            Mr[ii][j] = g_M[(size_t)(256 + j) * 2048 + d];
        }
    }

    for (int tt = 0; tt < 16; tt++) {
        const int t = t0 + tt;
        const float* xrow = &x[(size_t)(t * BATCH + b) * D_DIM];

        float acc[24];
#pragma unroll
        for (int c = 0; c < 24; c++) acc[c] = 0.f;

#pragma unroll
        for (int ii = 0; ii < 4; ii++) {
            float xv = xrow[tid + ii * 256];
#pragma unroll
            for (int j = 0; j < 8; j++) {
                acc[j]      = fmaf(Mk[ii][j], xv, acc[j]);
                acc[8 + j]  = fmaf(Mr[ii][j], xv, acc[8 + j]);
                acc[16 + j] = fmaf(Mq[ii][j], xv, acc[16 + j]);
            }
        }
#pragma unroll
        for (int off = 16; off > 0; off >>= 1)
#pragma unroll
            for (int c = 0; c < 24; c++)
                acc[c] += __shfl_down_sync(0xffffffffu, acc[c], off);

        if (lane == 0) {
#pragma unroll
            for (int c = 0; c < 24; c++) sred[warp * 24 + c] = acc[c];
        }
        __syncthreads();
        if (tid < 24) {
            float s = 0.f;
#pragma unroll
            for (int w = 0; w < 8; w++) s += sred[w * 24 + tid];
            g_coef[(size_t)(t * BATCH + b) * 24 + tid] = s;
        }
        __syncthreads();
    }
}

// ============================================================================
// Scan: EXACT R11 body (the formulation measured inside the 729us run).
// 128-thread blocks, 2 threads per row; two-sided clamp, num=e-1 batched rcp.
// ============================================================================
__global__ __launch_bounds__(128) void scan_kernel(
    const float* __restrict__ U0, float* __restrict__ out, int writeExtra)
{
    const int CH = 64;
    __shared__ float sc[CH * 24];
    __shared__ float ssc[CH];

    const int b    = blockIdx.y;
    const int tid  = threadIdx.x;
    const int lane = tid & 31, warp = tid >> 5;
    const int h    = lane >> 4;
    const int h4   = h * 4;
    const int i    = blockIdx.x * 64 + warp * 16 + (lane & 15);

    float U[4];
    {
        float4 u = *(const float4*)&U0[((size_t)b * N_DIM + i) * 8 + h4];
        U[0] = u.x; U[1] = u.y; U[2] = u.z; U[3] = u.w;
    }

    float vcur = g_v[(size_t)b * N_DIM + i];

    for (int tc = 0; tc < T_STEPS; tc += CH) {
        __syncthreads();
        if (tid < CH) {
            float ns = g_nsq[(size_t)(tc + tid) * BATCH + b];
            ssc[tid] = __fdividef(1.f, sqrtf(ns) + EPSV);
        }
        for (int idx = tid; idx < CH * 24; idx += 128) {
            int tt = idx / 24;
            sc[idx] = g_coef[(size_t)((tc + tt) * BATCH + b) * 24 + (idx - tt * 24)];
        }
        __syncthreads();

#pragma unroll 2
        for (int tt = 0; tt < CH; tt++) {
            const int t = tc + tt;
            float vnext = (t + 1 < T_STEPS)
                        ? g_v[(size_t)((t + 1) * BATCH + b) * N_DIM + i] : 0.f;
            const float* c = &sc[tt * 24];
            const float s = ssc[tt];

            float part = U[0] * c[h4];
#pragma unroll
            for (int j = 1; j < 4; j++) part = fmaf(U[j], c[h4 + j], part);
            float ret = (part + __shfl_xor_sync(0xffffffffu, part, 16)) * s;
            float dls = (vcur - ret) * s;

            float e[4], d[4], num[4];
#pragma unroll
            for (int j = 0; j < 4; j++) {
                float xx = fmaf(dls, c[8 + h4 + j], U[j]);
                xx = fminf(9.f, fmaxf(-9.f, xx));
                e[j]   = __expf(2.f * xx);
                d[j]   = e[j] + 1.f;
                num[j] = e[j] - 1.f;
            }
            float p01 = d[0] * d[1], p23 = d[2] * d[3];
            float r = rcp_approx(p01 * p23);
            float i01 = r * p23, i23 = r * p01;
            U[0] = num[0] * (i01 * d[1]);
            U[1] = num[1] * (i01 * d[0]);
            U[2] = num[2] * (i23 * d[3]);
            U[3] = num[3] * (i23 * d[2]);

            float p2 = U[0] * c[16 + h4];
#pragma unroll
            for (int j = 1; j < 4; j++) p2 = fmaf(U[j], c[16 + h4 + j], p2);
            float sq = p2 + __shfl_xor_sync(0xffffffffu, p2, 16);

            if (h == 0)
                out[(size_t)(t * BATCH + b) * N_DIM + i] = out_silu(sq);
            vcur = vnext;
        }
    }

    if (writeExtra) {
        float* uf = out + (size_t)M_ROWS * N_DIM + ((size_t)b * N_DIM + i) * 8 + h4;
        *(float4*)uf = make_float4(U[0], U[1], U[2], U[3]);
    }
}

// ============================================================================
struct AuxStreams {
    cudaStream_t s2;
    cudaEvent_t  fork, conv, join;
    AuxStreams() {
        cudaStreamCreate(&s2);
        cudaEventCreateWithFlags(&fork, cudaEventDisableTiming);
        cudaEventCreateWithFlags(&conv, cudaEventDisableTiming);
        cudaEventCreateWithFlags(&join, cudaEventDisableTiming);
    }
};

extern "C" void kernel_launch(void* const* d_in, const int* in_sizes, int n_in,
                              void* d_out, int out_size)
{
    const float* x   = (const float*)d_in[0];
    const float* Wk  = (const float*)d_in[1];
    const float* Wv  = (const float*)d_in[2];
    const float* Wq  = (const float*)d_in[3];
    const float* Wkr = (const float*)d_in[4];
    const float* U0  = (const float*)d_in[5];
    const float* V0  = (const float*)d_in[6];
    float* out = (float*)d_out;

    (void)in_sizes; (void)n_in;

    static AuxStreams aux;

    cudaFuncSetAttribute(gemm_virtual<0>,
                         cudaFuncAttributeMaxDynamicSharedMemorySize, 3 * STAGE);
    cudaFuncSetAttribute(gemm_virtual<1>,
                         cudaFuncAttributeMaxDynamicSharedMemorySize, 3 * STAGE);

    // Chain B (s2): prep -> coef; then norm-GEMM after convert completes.
    cudaEventRecord(aux.fork, 0);
    cudaStreamWaitEvent(aux.s2, aux.fork, 0);
    prep_kernel<<<dim3(16, 33), 128, 0, aux.s2>>>(V0, Wk, Wq, Wkr);
    coef_kernel<<<dim3(T_STEPS / 16, BATCH), 256, 0, aux.s2>>>(x);

    // Chain A (stream 0): convert -> v-GEMM (fp16, 1 product)
    convert_kernel<<<18448, 256>>>(x, Wk, Wv);
    cudaEventRecord(aux.conv, 0);
    gemm_virtual<0><<<dim3(8, 128), 256, 3 * STAGE>>>();

    // norm-GEMM (fp16, 1 product) on s2, co-scheduled with v-GEMM
    cudaStreamWaitEvent(aux.s2, aux.conv, 0);
    gemm_virtual<1><<<dim3(8, 128), 256, 3 * STAGE, aux.s2>>>();
    cudaEventRecord(aux.join, aux.s2);

    // Join, then scan
    cudaStreamWaitEvent(0, aux.join, 0);
    const int extraElems = 2 * BATCH * N_DIM * R_DIM;
    int writeExtra = (out_size >= M_ROWS * N_DIM + extraElems) ? 1 : 0;
    scan_kernel<<<dim3(N_DIM / 64, BATCH), 128>>>(U0, out, writeExtra);

    if (writeExtra) {
        cudaMemcpyAsync(out + (size_t)M_ROWS * N_DIM + BATCH * N_DIM * R_DIM,
                        V0, (size_t)BATCH * N_DIM * R_DIM * sizeof(float),
                        cudaMemcpyDeviceToDevice, 0);
    }
}

// round 14
// speedup vs baseline: 1.4113x; 1.0095x over previous
#include <cuda_runtime.h>
#include <cuda_fp16.h>
#include <math.h>
#include <stdint.h>

#define T_STEPS 512
#define BATCH   32
#define D_DIM   1024
#define N_DIM   1024
#define R_DIM   8
#define M_ROWS  (T_STEPS*BATCH)   /* 16384 */
#define EPSV    1e-6f
#define KC      64
#define STAGE   32768             /* A-part @0 (16K), B-part @16K */

// ---------------- scratch (static device arrays; no cudaMalloc) ------------
__device__ float g_v[M_ROWS * N_DIM];
__device__ float g_coef[M_ROWS * 24];
__device__ float g_nsq[M_ROWS];
__device__ float g_M[384 * 2048];
__device__ __half g_xh[M_ROWS * D_DIM];
__device__ __half g_wk[D_DIM * D_DIM];
__device__ __half g_wv[D_DIM * D_DIM];

// ---------------- transcendentals -------------------------------------------
__device__ __forceinline__ float out_silu(float s) {
    float xs = fminf(30.f, fmaxf(-30.f, s));
    float e  = __expf(-xs);
    return s * s * __fdividef(1.f, 1.f + e);
}
__device__ __forceinline__ float rcp_approx(float x) {
    float r;
    asm("rcp.approx.f32 %0, %1;" : "=f"(r) : "f"(x));
    return r;
}

// ---------------- PTX helpers ------------------------------------------------
__device__ __forceinline__ uint32_t smem_u32(const void* p) {
    uint32_t a;
    asm("{ .reg .u64 t; cvta.to.shared.u64 t, %1; cvt.u32.u64 %0, t; }"
        : "=r"(a) : "l"(p));
    return a;
}
__device__ __forceinline__ void cp16(uint32_t s, const void* g) {
    asm volatile("cp.async.cg.shared.global [%0], [%1], 16;"
                 :: "r"(s), "l"(g) : "memory");
}
#define LDSM_X4(r0, r1, r2, r3, addr) \
    asm volatile("ldmatrix.sync.aligned.m8n8.x4.shared.b16 {%0,%1,%2,%3}, [%4];" \
        : "=r"(r0), "=r"(r1), "=r"(r2), "=r"(r3) : "r"(addr))
#define MMA_F16(d, a, b0, b1) \
    asm volatile("mma.sync.aligned.m16n8k16.row.col.f32.f16.f16.f32 " \
        "{%0,%1,%2,%3},{%4,%5,%6,%7},{%8,%9},{%0,%1,%2,%3};" \
        : "+f"((d)[0]), "+f"((d)[1]), "+f"((d)[2]), "+f"((d)[3]) \
        : "r"((a)[0]), "r"((a)[1]), "r"((a)[2]), "r"((a)[3]), "r"(b0), "r"(b1))

// ============================================================================
// Convert: x -> fp16, Wk -> fp16, Wv -> fp16; zero g_nsq
// ============================================================================
__global__ __launch_bounds__(256) void convert_kernel(
    const float* __restrict__ x, const float* __restrict__ Wk,
    const float* __restrict__ Wv)
{
    int bid = blockIdx.x;
    const float* src;
    __half* dst;
    size_t idx;
    if (bid < 16384) {
        src = x; dst = g_xh; idx = (size_t)bid * 256 + threadIdx.x;
    } else if (bid < 17408) {
        src = Wk; dst = g_wk; idx = (size_t)(bid - 16384) * 256 + threadIdx.x;
    } else if (bid < 18432) {
        src = Wv; dst = g_wv; idx = (size_t)(bid - 17408) * 256 + threadIdx.x;
    } else {
        size_t z = (size_t)(bid - 18432) * 256 + threadIdx.x;
        ((float4*)g_nsq)[z] = make_float4(0.f, 0.f, 0.f, 0.f);
        return;
    }
    float4 v = ((const float4*)src)[idx];
    ((__half2*)dst)[idx*2]   = __half2{__float2half_rn(v.x), __float2half_rn(v.y)};
    ((__half2*)dst)[idx*2+1] = __half2{__float2half_rn(v.z), __float2half_rn(v.w)};
}

// ============================================================================
// Prep (plain fp32): g_M[p][d] = sum_n P[p][n]*Wk[n][d]; [.][1024+d] for Wq.
// ============================================================================
__global__ __launch_bounds__(128) void prep_kernel(
    const float* __restrict__ V0, const float* __restrict__ Wk,
    const float* __restrict__ Wq, const float* __restrict__ Wkr)
{
    __shared__ float sP[8][128];
    const int dx  = blockIdx.x;
    const int py  = blockIdx.y;
    const int tid = threadIdx.x;
    const float* W = (dx < 8) ? Wk : Wq;
    const int d = (dx & 7) * 128 + tid;

    float acc[8];
#pragma unroll
    for (int j = 0; j < 8; j++) acc[j] = 0.f;

    for (int n0 = 0; n0 < N_DIM; n0 += 128) {
        __syncthreads();
        for (int idx = tid; idx < 1024; idx += 128) {
            int j = idx >> 7, n = idx & 127;
            float v;
            if (py < 32) v = V0[((size_t)py * N_DIM + n0 + n) * 8 + j];
            else         v = Wkr[(size_t)j * N_DIM + n0 + n];
            sP[j][n] = v;
        }
        __syncthreads();
#pragma unroll 4
        for (int n = 0; n < 128; n++) {
            float w = W[(size_t)(n0 + n) * D_DIM + d];
#pragma unroll
            for (int j = 0; j < 8; j++) acc[j] = fmaf(sP[j][n], w, acc[j]);
        }
    }

    const int prow = py * 8;
    const int dcol = ((dx < 8) ? 0 : 1024) + (dx & 7) * 128 + tid;
#pragma unroll
    for (int j = 0; j < 8; j++)
        g_M[(size_t)(prow + j) * 2048 + dcol] = acc[j];
}

// ============================================================================
// Merged single-product fp16 HMMA GEMM, one launch, grid (8,128,2):
//   z=0: xh*Wv -> store g_v ;  z=1: xh*Wk -> row SSQ -> atomicAdd g_nsq.
// 16 K-chunks, 3-stage pipeline (96KB), 2 CTAs/SM.
// ============================================================================
__device__ __forceinline__ void fill_vstage(uint32_t st, int chunk, int tid,
                                            int mt, int nt,
                                            const __half* __restrict__ B0)
{
    const __half* A = g_xh + (size_t)mt * 128 * D_DIM + chunk * KC;
    const __half* B = B0 + (size_t)nt * 128 * D_DIM + chunk * KC;
#pragma unroll
    for (int v = tid; v < 1024; v += 256) {
        int row = v >> 3, c = v & 7;
        uint32_t so = (uint32_t)(row * 128 + ((c * 16) ^ ((row & 7) << 4)));
        size_t go = (size_t)row * D_DIM + c * 8;
        cp16(st + so,         A + go);
        cp16(st + 16384 + so, B + go);
    }
}

__global__ __launch_bounds__(256, 2) void gemm_merged()
{
    constexpr int NCHUNK = 16;
    extern __shared__ char smem[];
    const uint32_t sb = smem_u32(smem);
    const int tid  = threadIdx.x;
    const int lane = tid & 31, wid = tid >> 5;
    const int wm = wid >> 1, wn = wid & 1;
    const int nt = blockIdx.x, mt = blockIdx.y;
    const bool isV = (blockIdx.z == 0);
    const __half* B0 = isV ? g_wv : g_wk;

    const uint32_t aRowOff = (uint32_t)((wm * 32 + (lane & 15)) * 128);
    const uint32_t aSeg    = (uint32_t)((lane >> 4) * 16);
    const uint32_t bRowOff = (uint32_t)((wn * 64 + ((lane >> 4) << 3) + (lane & 7)) * 128);
    const uint32_t bSeg    = (uint32_t)(((lane >> 3) & 1) * 16);
    const uint32_t xorm    = (uint32_t)((lane & 7) << 4);

    float acc[2][8][4];
#pragma unroll
    for (int i = 0; i < 2; i++)
#pragma unroll
        for (int j = 0; j < 8; j++)
#pragma unroll
            for (int e = 0; e < 4; e++) acc[i][j][e] = 0.f;

    fill_vstage(sb, 0, tid, mt, nt, B0);
    asm volatile("cp.async.commit_group;" ::: "memory");
    fill_vstage(sb + STAGE, 1, tid, mt, nt, B0);
    asm volatile("cp.async.commit_group;" ::: "memory");

    for (int c = 0; c < NCHUNK; c++) {
        if (c + 2 < NCHUNK) {
            fill_vstage(sb + ((c + 2) % 3) * STAGE, c + 2, tid, mt, nt, B0);
            asm volatile("cp.async.commit_group;" ::: "memory");
            asm volatile("cp.async.wait_group 2;" ::: "memory");
        } else if (c + 1 < NCHUNK) {
            asm volatile("cp.async.wait_group 1;" ::: "memory");
        } else {
            asm volatile("cp.async.wait_group 0;" ::: "memory");
        }
        __syncthreads();

        const uint32_t sA = sb + (c % 3) * STAGE;
        const uint32_t sB = sA + 16384;

#pragma unroll
        for (int ks = 0; ks < 4; ks++) {
            const uint32_t kb = (uint32_t)(ks * 32);
            uint32_t a[2][4];
#pragma unroll
            for (int i = 0; i < 2; i++) {
                uint32_t ad = sA + i * 2048 + aRowOff + ((kb + aSeg) ^ xorm);
                LDSM_X4(a[i][0], a[i][1], a[i][2], a[i][3], ad);
            }
#pragma unroll
            for (int jp = 0; jp < 4; jp++) {
                uint32_t b0, b1, b2, b3;
                uint32_t bd = sB + jp * 2048 + bRowOff + ((kb + bSeg) ^ xorm);
                LDSM_X4(b0, b1, b2, b3, bd);
#pragma unroll
                for (int i = 0; i < 2; i++) {
                    MMA_F16(acc[i][2*jp],     a[i], b0, b1);
                    MMA_F16(acc[i][2*jp + 1], a[i], b2, b3);
                }
            }
        }
        __syncthreads();
    }

    if (isV) {
#pragma unroll
        for (int i = 0; i < 2; i++) {
            const int r0 = mt * 128 + wm * 32 + i * 16 + (lane >> 2);
#pragma unroll
            for (int j = 0; j < 8; j++) {
                const int col = nt * 128 + wn * 64 + j * 8 + (lane & 3) * 2;
                *(float2*)&g_v[(size_t)r0 * N_DIM + col] =
                    make_float2(acc[i][j][0], acc[i][j][1]);
                *(float2*)&g_v[(size_t)(r0 + 8) * N_DIM + col] =
                    make_float2(acc[i][j][2], acc[i][j][3]);
            }
        }
    } else {
#pragma unroll
        for (int i = 0; i < 2; i++) {
            float s0 = 0.f, s1 = 0.f;
#pragma unroll
            for (int j = 0; j < 8; j++) {
                s0 = fmaf(acc[i][j][0], acc[i][j][0], s0);
                s0 = fmaf(acc[i][j][1], acc[i][j][1], s0);
                s1 = fmaf(acc[i][j][2], acc[i][j][2], s1);
                s1 = fmaf(acc[i][j][3], acc[i][j][3], s1);
            }
            s0 += __shfl_xor_sync(0xffffffffu, s0, 1);
            s0 += __shfl_xor_sync(0xffffffffu, s0, 2);
            s1 += __shfl_xor_sync(0xffffffffu, s1, 1);
            s1 += __shfl_xor_sync(0xffffffffu, s1, 2);
            const int r0 = mt * 128 + wm * 32 + i * 16 + (lane >> 2);
            if ((lane & 3) == 0) {
                atomicAdd(&g_nsq[r0],     s0);
                atomicAdd(&g_nsq[r0 + 8], s1);
            }
        }
    }
}

// ============================================================================
// Coef: per (t,b), 24 raw dots of x against fused M rows (Vtk | kr | Vtq)
// ============================================================================
__global__ __launch_bounds__(256) void coef_kernel(const float* __restrict__ x)
{
    __shared__ float sred[8 * 24];

    const int b  = blockIdx.y;
    const int t0 = blockIdx.x * 16;
    const int tid = threadIdx.x;
    const int lane = tid & 31, warp = tid >> 5;

    float Mk[4][8], Mr[4][8], Mq[4][8];
#pragma unroll
    for (int ii = 0; ii < 4; ii++) {
        int d = tid + ii * 256;
#pragma unroll
        for (int j = 0; j < 8; j++) {
            Mk[ii][j] = g_M[(size_t)(b * 8 + j) * 2048 + d];
            Mq[ii][j] = g_M[(size_t)(b * 8 + j) * 2048 + 1024 + d];
            Mr[ii][j] = g_M[(size_t)(256 + j) * 2048 + d];
        }
    }

    for (int tt = 0; tt < 16; tt++) {
        const int t = t0 + tt;
        const float* xrow = &x[(size_t)(t * BATCH + b) * D_DIM];

        float acc[24];
#pragma unroll
        for (int c = 0; c < 24; c++) acc[c] = 0.f;

#pragma unroll
        for (int ii = 0; ii < 4; ii++) {
            float xv = xrow[tid + ii * 256];
#pragma unroll
            for (int j = 0; j < 8; j++) {
                acc[j]      = fmaf(Mk[ii][j], xv, acc[j]);
                acc[8 + j]  = fmaf(Mr[ii][j], xv, acc[8 + j]);
                acc[16 + j] = fmaf(Mq[ii][j], xv, acc[16 + j]);
            }
        }
#pragma unroll
        for (int off = 16; off > 0; off >>= 1)
#pragma unroll
            for (int c = 0; c < 24; c++)
                acc[c] += __shfl_down_sync(0xffffffffu, acc[c], off);

        if (lane == 0) {
#pragma unroll
            for (int c = 0; c < 24; c++) sred[warp * 24 + c] = acc[c];
        }
        __syncthreads();
        if (tid < 24) {
            float s = 0.f;
#pragma unroll
            for (int w = 0; w < 8; w++) s += sred[w * 24 + tid];
            g_coef[(size_t)(t * BATCH + b) * 24 + tid] = s;
        }
        __syncthreads();
    }
}

// ============================================================================
// Scan: EXACT R13 body (measured-good formulation). Do not touch.
// ============================================================================
__global__ __launch_bounds__(128) void scan_kernel(
    const float* __restrict__ U0, float* __restrict__ out, int writeExtra)
{
    const int CH = 64;
    __shared__ float sc[CH * 24];
    __shared__ float ssc[CH];

    const int b    = blockIdx.y;
    const int tid  = threadIdx.x;
    const int lane = tid & 31, warp = tid >> 5;
    const int h    = lane >> 4;
    const int h4   = h * 4;
    const int i    = blockIdx.x * 64 + warp * 16 + (lane & 15);

    float U[4];
    {
        float4 u = *(const float4*)&U0[((size_t)b * N_DIM + i) * 8 + h4];
        U[0] = u.x; U[1] = u.y; U[2] = u.z; U[3] = u.w;
    }

    float vcur = g_v[(size_t)b * N_DIM + i];

    for (int tc = 0; tc < T_STEPS; tc += CH) {
        __syncthreads();
        if (tid < CH) {
            float ns = g_nsq[(size_t)(tc + tid) * BATCH + b];
            ssc[tid] = __fdividef(1.f, sqrtf(ns) + EPSV);
        }
        for (int idx = tid; idx < CH * 24; idx += 128) {
            int tt = idx / 24;
            sc[idx] = g_coef[(size_t)((tc + tt) * BATCH + b) * 24 + (idx - tt * 24)];
        }
        __syncthreads();

#pragma unroll 2
        for (int tt = 0; tt < CH; tt++) {
            const int t = tc + tt;
            float vnext = (t + 1 < T_STEPS)
                        ? g_v[(size_t)((t + 1) * BATCH + b) * N_DIM + i] : 0.f;
            const float* c = &sc[tt * 24];
            const float s = ssc[tt];

            float part = U[0] * c[h4];
#pragma unroll
            for (int j = 1; j < 4; j++) part = fmaf(U[j], c[h4 + j], part);
            float ret = (part + __shfl_xor_sync(0xffffffffu, part, 16)) * s;
            float dls = (vcur - ret) * s;

            float e[4], d[4], num[4];
#pragma unroll
            for (int j = 0; j < 4; j++) {
                float xx = fmaf(dls, c[8 + h4 + j], U[j]);
                xx = fminf(9.f, fmaxf(-9.f, xx));
                e[j]   = __expf(2.f * xx);
                d[j]   = e[j] + 1.f;
                num[j] = e[j] - 1.f;
            }
            float p01 = d[0] * d[1], p23 = d[2] * d[3];
            float r = rcp_approx(p01 * p23);
            float i01 = r * p23, i23 = r * p01;
            U[0] = num[0] * (i01 * d[1]);
            U[1] = num[1] * (i01 * d[0]);
            U[2] = num[2] * (i23 * d[3]);
            U[3] = num[3] * (i23 * d[2]);

            float p2 = U[0] * c[16 + h4];
#pragma unroll
            for (int j = 1; j < 4; j++) p2 = fmaf(U[j], c[16 + h4 + j], p2);
            float sq = p2 + __shfl_xor_sync(0xffffffffu, p2, 16);

            if (h == 0)
                out[(size_t)(t * BATCH + b) * N_DIM + i] = out_silu(sq);
            vcur = vnext;
        }
    }

    if (writeExtra) {
        float* uf = out + (size_t)M_ROWS * N_DIM + ((size_t)b * N_DIM + i) * 8 + h4;
        *(float4*)uf = make_float4(U[0], U[1], U[2], U[3]);
    }
}

// ============================================================================
struct AuxStreams {
    cudaStream_t s2;
    cudaEvent_t  fork, join;
    AuxStreams() {
        cudaStreamCreate(&s2);
        cudaEventCreateWithFlags(&fork, cudaEventDisableTiming);
        cudaEventCreateWithFlags(&join, cudaEventDisableTiming);
    }
};

extern "C" void kernel_launch(void* const* d_in, const int* in_sizes, int n_in,
                              void* d_out, int out_size)
{
    const float* x   = (const float*)d_in[0];
    const float* Wk  = (const float*)d_in[1];
    const float* Wv  = (const float*)d_in[2];
    const float* Wq  = (const float*)d_in[3];
    const float* Wkr = (const float*)d_in[4];
    const float* U0  = (const float*)d_in[5];
    const float* V0  = (const float*)d_in[6];
    float* out = (float*)d_out;

    (void)in_sizes; (void)n_in;

    static AuxStreams aux;

    cudaFuncSetAttribute(gemm_merged,
                         cudaFuncAttributeMaxDynamicSharedMemorySize, 3 * STAGE);

    // Chain B (s2): prep -> coef (fp32 pipes; independent of chain A)
    cudaEventRecord(aux.fork, 0);
    cudaStreamWaitEvent(aux.s2, aux.fork, 0);
    prep_kernel<<<dim3(16, 33), 128, 0, aux.s2>>>(V0, Wk, Wq, Wkr);
    coef_kernel<<<dim3(T_STEPS / 16, BATCH), 256, 0, aux.s2>>>(x);
    cudaEventRecord(aux.join, aux.s2);

    // Chain A (stream 0): convert -> merged GEMM (v + norm in one launch)
    convert_kernel<<<18448, 256>>>(x, Wk, Wv);
    gemm_merged<<<dim3(8, 128, 2), 256, 3 * STAGE>>>();

    // Join, then scan
    cudaStreamWaitEvent(0, aux.join, 0);
    const int extraElems = 2 * BATCH * N_DIM * R_DIM;
    int writeExtra = (out_size >= M_ROWS * N_DIM + extraElems) ? 1 : 0;
    scan_kernel<<<dim3(N_DIM / 64, BATCH), 128>>>(U0, out, writeExtra);

    if (writeExtra) {
        cudaMemcpyAsync(out + (size_t)M_ROWS * N_DIM + BATCH * N_DIM * R_DIM,
                        V0, (size_t)BATCH * N_DIM * R_DIM * sizeof(float),
                        cudaMemcpyDeviceToDevice, 0);
    }
}

// round 15
// speedup vs baseline: 1.5511x; 1.0991x over previous
#include <cuda_runtime.h>
#include <cuda_fp16.h>
#include <math.h>
#include <stdint.h>

#define T_STEPS 512
#define BATCH   32
#define D_DIM   1024
#define N_DIM   1024
#define R_DIM   8
#define M_ROWS  (T_STEPS*BATCH)   /* 16384 */
#define EPSV    1e-6f
#define KC      64
#define STAGE   32768             /* A-part @0 (16K), B-part @16K */

// ---------------- scratch (static device arrays; no cudaMalloc) ------------
__device__ float g_v[M_ROWS * N_DIM];
__device__ float g_coef[M_ROWS * 24];
__device__ float g_nsq[M_ROWS];
__device__ float g_M[384 * 2048];
__device__ __half g_xh[M_ROWS * D_DIM];
__device__ __half g_wk[D_DIM * D_DIM];
__device__ __half g_wv[D_DIM * D_DIM];

// ---------------- transcendentals -------------------------------------------
__device__ __forceinline__ float out_silu(float s) {
    float xs = fminf(30.f, fmaxf(-30.f, s));
    float e  = __expf(-xs);
    return s * s * __fdividef(1.f, 1.f + e);
}
__device__ __forceinline__ float rcp_approx(float x) {
    float r;
    asm("rcp.approx.f32 %0, %1;" : "=f"(r) : "f"(x));
    return r;
}

// ---------------- PTX helpers ------------------------------------------------
__device__ __forceinline__ uint32_t smem_u32(const void* p) {
    uint32_t a;
    asm("{ .reg .u64 t; cvta.to.shared.u64 t, %1; cvt.u32.u64 %0, t; }"
        : "=r"(a) : "l"(p));
    return a;
}
__device__ __forceinline__ void cp16(uint32_t s, const void* g) {
    asm volatile("cp.async.cg.shared.global [%0], [%1], 16;"
                 :: "r"(s), "l"(g) : "memory");
}
#define LDSM_X4(r0, r1, r2, r3, addr) \
    asm volatile("ldmatrix.sync.aligned.m8n8.x4.shared.b16 {%0,%1,%2,%3}, [%4];" \
        : "=r"(r0), "=r"(r1), "=r"(r2), "=r"(r3) : "r"(addr))
#define MMA_F16(d, a, b0, b1) \
    asm volatile("mma.sync.aligned.m16n8k16.row.col.f32.f16.f16.f32 " \
        "{%0,%1,%2,%3},{%4,%5,%6,%7},{%8,%9},{%0,%1,%2,%3};" \
        : "+f"((d)[0]), "+f"((d)[1]), "+f"((d)[2]), "+f"((d)[3]) \
        : "r"((a)[0]), "r"((a)[1]), "r"((a)[2]), "r"((a)[3]), "r"(b0), "r"(b1))

// ============================================================================
// Convert: x -> fp16, Wk -> fp16, Wv -> fp16; zero g_nsq
// ============================================================================
__global__ __launch_bounds__(256) void convert_kernel(
    const float* __restrict__ x, const float* __restrict__ Wk,
    const float* __restrict__ Wv)
{
    int bid = blockIdx.x;
    const float* src;
    __half* dst;
    size_t idx;
    if (bid < 16384) {
        src = x; dst = g_xh; idx = (size_t)bid * 256 + threadIdx.x;
    } else if (bid < 17408) {
        src = Wk; dst = g_wk; idx = (size_t)(bid - 16384) * 256 + threadIdx.x;
    } else if (bid < 18432) {
        src = Wv; dst = g_wv; idx = (size_t)(bid - 17408) * 256 + threadIdx.x;
    } else {
        size_t z = (size_t)(bid - 18432) * 256 + threadIdx.x;
        ((float4*)g_nsq)[z] = make_float4(0.f, 0.f, 0.f, 0.f);
        return;
    }
    float4 v = ((const float4*)src)[idx];
    ((__half2*)dst)[idx*2]   = __half2{__float2half_rn(v.x), __float2half_rn(v.y)};
    ((__half2*)dst)[idx*2+1] = __half2{__float2half_rn(v.z), __float2half_rn(v.w)};
}

// ============================================================================
// Prep (plain fp32): g_M[p][d] = sum_n P[p][n]*Wk[n][d]; [.][1024+d] for Wq.
// ============================================================================
__global__ __launch_bounds__(128) void prep_kernel(
    const float* __restrict__ V0, const float* __restrict__ Wk,
    const float* __restrict__ Wq, const float* __restrict__ Wkr)
{
    __shared__ float sP[8][128];
    const int dx  = blockIdx.x;
    const int py  = blockIdx.y;
    const int tid = threadIdx.x;
    const float* W = (dx < 8) ? Wk : Wq;
    const int d = (dx & 7) * 128 + tid;

    float acc[8];
#pragma unroll
    for (int j = 0; j < 8; j++) acc[j] = 0.f;

    for (int n0 = 0; n0 < N_DIM; n0 += 128) {
        __syncthreads();
        for (int idx = tid; idx < 1024; idx += 128) {
            int j = idx >> 7, n = idx & 127;
            float v;
            if (py < 32) v = V0[((size_t)py * N_DIM + n0 + n) * 8 + j];
            else         v = Wkr[(size_t)j * N_DIM + n0 + n];
            sP[j][n] = v;
        }
        __syncthreads();
#pragma unroll 4
        for (int n = 0; n < 128; n++) {
            float w = W[(size_t)(n0 + n) * D_DIM + d];
#pragma unroll
            for (int j = 0; j < 8; j++) acc[j] = fmaf(sP[j][n], w, acc[j]);
        }
    }

    const int prow = py * 8;
    const int dcol = ((dx < 8) ? 0 : 1024) + (dx & 7) * 128 + tid;
#pragma unroll
    for (int j = 0; j < 8; j++)
        g_M[(size_t)(prow + j) * 2048 + dcol] = acc[j];
}

// ============================================================================
// Merged single-product fp16 HMMA GEMM, one launch, grid (8,128,2):
//   z=0: xh*Wv -> store g_v ;  z=1: xh*Wk -> row SSQ -> atomicAdd g_nsq.
// 16 K-chunks, 3-stage pipeline (96KB), 2 CTAs/SM.
// ============================================================================
__device__ __forceinline__ void fill_vstage(uint32_t st, int chunk, int tid,
                                            int mt, int nt,
                                            const __half* __restrict__ B0)
{
    const __half* A = g_xh + (size_t)mt * 128 * D_DIM + chunk * KC;
    const __half* B = B0 + (size_t)nt * 128 * D_DIM + chunk * KC;
#pragma unroll
    for (int v = tid; v < 1024; v += 256) {
        int row = v >> 3, c = v & 7;
        uint32_t so = (uint32_t)(row * 128 + ((c * 16) ^ ((row & 7) << 4)));
        size_t go = (size_t)row * D_DIM + c * 8;
        cp16(st + so,         A + go);
        cp16(st + 16384 + so, B + go);
    }
}

__global__ __launch_bounds__(256, 2) void gemm_merged()
{
    constexpr int NCHUNK = 16;
    extern __shared__ char smem[];
    const uint32_t sb = smem_u32(smem);
    const int tid  = threadIdx.x;
    const int lane = tid & 31, wid = tid >> 5;
    const int wm = wid >> 1, wn = wid & 1;
    const int nt = blockIdx.x, mt = blockIdx.y;
    const bool isV = (blockIdx.z == 0);
    const __half* B0 = isV ? g_wv : g_wk;

    const uint32_t aRowOff = (uint32_t)((wm * 32 + (lane & 15)) * 128);
    const uint32_t aSeg    = (uint32_t)((lane >> 4) * 16);
    const uint32_t bRowOff = (uint32_t)((wn * 64 + ((lane >> 4) << 3) + (lane & 7)) * 128);
    const uint32_t bSeg    = (uint32_t)(((lane >> 3) & 1) * 16);
    const uint32_t xorm    = (uint32_t)((lane & 7) << 4);

    float acc[2][8][4];
#pragma unroll
    for (int i = 0; i < 2; i++)
#pragma unroll
        for (int j = 0; j < 8; j++)
#pragma unroll
            for (int e = 0; e < 4; e++) acc[i][j][e] = 0.f;

    fill_vstage(sb, 0, tid, mt, nt, B0);
    asm volatile("cp.async.commit_group;" ::: "memory");
    fill_vstage(sb + STAGE, 1, tid, mt, nt, B0);
    asm volatile("cp.async.commit_group;" ::: "memory");

    for (int c = 0; c < NCHUNK; c++) {
        if (c + 2 < NCHUNK) {
            fill_vstage(sb + ((c + 2) % 3) * STAGE, c + 2, tid, mt, nt, B0);
            asm volatile("cp.async.commit_group;" ::: "memory");
            asm volatile("cp.async.wait_group 2;" ::: "memory");
        } else if (c + 1 < NCHUNK) {
            asm volatile("cp.async.wait_group 1;" ::: "memory");
        } else {
            asm volatile("cp.async.wait_group 0;" ::: "memory");
        }
        __syncthreads();

        const uint32_t sA = sb + (c % 3) * STAGE;
        const uint32_t sB = sA + 16384;

#pragma unroll
        for (int ks = 0; ks < 4; ks++) {
            const uint32_t kb = (uint32_t)(ks * 32);
            uint32_t a[2][4];
#pragma unroll
            for (int i = 0; i < 2; i++) {
                uint32_t ad = sA + i * 2048 + aRowOff + ((kb + aSeg) ^ xorm);
                LDSM_X4(a[i][0], a[i][1], a[i][2], a[i][3], ad);
            }
#pragma unroll
            for (int jp = 0; jp < 4; jp++) {
                uint32_t b0, b1, b2, b3;
                uint32_t bd = sB + jp * 2048 + bRowOff + ((kb + bSeg) ^ xorm);
                LDSM_X4(b0, b1, b2, b3, bd);
#pragma unroll
                for (int i = 0; i < 2; i++) {
                    MMA_F16(acc[i][2*jp],     a[i], b0, b1);
                    MMA_F16(acc[i][2*jp + 1], a[i], b2, b3);
                }
            }
        }
        __syncthreads();
    }

    if (isV) {
#pragma unroll
        for (int i = 0; i < 2; i++) {
            const int r0 = mt * 128 + wm * 32 + i * 16 + (lane >> 2);
#pragma unroll
            for (int j = 0; j < 8; j++) {
                const int col = nt * 128 + wn * 64 + j * 8 + (lane & 3) * 2;
                *(float2*)&g_v[(size_t)r0 * N_DIM + col] =
                    make_float2(acc[i][j][0], acc[i][j][1]);
                *(float2*)&g_v[(size_t)(r0 + 8) * N_DIM + col] =
                    make_float2(acc[i][j][2], acc[i][j][3]);
            }
        }
    } else {
#pragma unroll
        for (int i = 0; i < 2; i++) {
            float s0 = 0.f, s1 = 0.f;
#pragma unroll
            for (int j = 0; j < 8; j++) {
                s0 = fmaf(acc[i][j][0], acc[i][j][0], s0);
                s0 = fmaf(acc[i][j][1], acc[i][j][1], s0);
                s1 = fmaf(acc[i][j][2], acc[i][j][2], s1);
                s1 = fmaf(acc[i][j][3], acc[i][j][3], s1);
            }
            s0 += __shfl_xor_sync(0xffffffffu, s0, 1);
            s0 += __shfl_xor_sync(0xffffffffu, s0, 2);
            s1 += __shfl_xor_sync(0xffffffffu, s1, 1);
            s1 += __shfl_xor_sync(0xffffffffu, s1, 2);
            const int r0 = mt * 128 + wm * 32 + i * 16 + (lane >> 2);
            if ((lane & 3) == 0) {
                atomicAdd(&g_nsq[r0],     s0);
                atomicAdd(&g_nsq[r0 + 8], s1);
            }
        }
    }
}

// ============================================================================
// Coef: per (t,b), 24 raw dots of x against fused M rows (Vtk | kr | Vtq)
// ============================================================================
__global__ __launch_bounds__(256) void coef_kernel(const float* __restrict__ x)
{
    __shared__ float sred[8 * 24];

    const int b  = blockIdx.y;
    const int t0 = blockIdx.x * 16;
    const int tid = threadIdx.x;
    const int lane = tid & 31, warp = tid >> 5;

    float Mk[4][8], Mr[4][8], Mq[4][8];
#pragma unroll
    for (int ii = 0; ii < 4; ii++) {
        int d = tid + ii * 256;
#pragma unroll
        for (int j = 0; j < 8; j++) {
            Mk[ii][j] = g_M[(size_t)(b * 8 + j) * 2048 + d];
            Mq[ii][j] = g_M[(size_t)(b * 8 + j) * 2048 + 1024 + d];
            Mr[ii][j] = g_M[(size_t)(256 + j) * 2048 + d];
        }
    }

    for (int tt = 0; tt < 16; tt++) {
        const int t = t0 + tt;
        const float* xrow = &x[(size_t)(t * BATCH + b) * D_DIM];

        float acc[24];
#pragma unroll
        for (int c = 0; c < 24; c++) acc[c] = 0.f;

#pragma unroll
        for (int ii = 0; ii < 4; ii++) {
            float xv = xrow[tid + ii * 256];
#pragma unroll
            for (int j = 0; j < 8; j++) {
                acc[j]      = fmaf(Mk[ii][j], xv, acc[j]);
                acc[8 + j]  = fmaf(Mr[ii][j], xv, acc[8 + j]);
                acc[16 + j] = fmaf(Mq[ii][j], xv, acc[16 + j]);
            }
        }
#pragma unroll
        for (int off = 16; off > 0; off >>= 1)
#pragma unroll
            for (int c = 0; c < 24; c++)
                acc[c] += __shfl_down_sync(0xffffffffu, acc[c], off);

        if (lane == 0) {
#pragma unroll
            for (int c = 0; c < 24; c++) sred[warp * 24 + c] = acc[c];
        }
        __syncthreads();
        if (tid < 24) {
            float s = 0.f;
#pragma unroll
            for (int w = 0; w < 8; w++) s += sred[w * 24 + tid];
            g_coef[(size_t)(t * BATCH + b) * 24 + tid] = s;
        }
        __syncthreads();
    }
}

// ============================================================================
// Scan: EXACT R13 body (measured-good formulation). Do not touch.
// ============================================================================
__global__ __launch_bounds__(128) void scan_kernel(
    const float* __restrict__ U0, float* __restrict__ out, int writeExtra)
{
    const int CH = 64;
    __shared__ float sc[CH * 24];
    __shared__ float ssc[CH];

    const int b    = blockIdx.y;
    const int tid  = threadIdx.x;
    const int lane = tid & 31, warp = tid >> 5;
    const int h    = lane >> 4;
    const int h4   = h * 4;
    const int i    = blockIdx.x * 64 + warp * 16 + (lane & 15);

    float U[4];
    {
        float4 u = *(const float4*)&U0[((size_t)b * N_DIM + i) * 8 + h4];
        U[0] = u.x; U[1] = u.y; U[2] = u.z; U[3] = u.w;
    }

    float vcur = g_v[(size_t)b * N_DIM + i];

    for (int tc = 0; tc < T_STEPS; tc += CH) {
        __syncthreads();
        if (tid < CH) {
            float ns = g_nsq[(size_t)(tc + tid) * BATCH + b];
            ssc[tid] = __fdividef(1.f, sqrtf(ns) + EPSV);
        }
        for (int idx = tid; idx < CH * 24; idx += 128) {
            int tt = idx / 24;
            sc[idx] = g_coef[(size_t)((tc + tt) * BATCH + b) * 24 + (idx - tt * 24)];
        }
        __syncthreads();

#pragma unroll 2
        for (int tt = 0; tt < CH; tt++) {
            const int t = tc + tt;
            float vnext = (t + 1 < T_STEPS)
                        ? g_v[(size_t)((t + 1) * BATCH + b) * N_DIM + i] : 0.f;
            const float* c = &sc[tt * 24];
            const float s = ssc[tt];

            float part = U[0] * c[h4];
#pragma unroll
            for (int j = 1; j < 4; j++) part = fmaf(U[j], c[h4 + j], part);
            float ret = (part + __shfl_xor_sync(0xffffffffu, part, 16)) * s;
            float dls = (vcur - ret) * s;

            float e[4], d[4], num[4];
#pragma unroll
            for (int j = 0; j < 4; j++) {
                float xx = fmaf(dls, c[8 + h4 + j], U[j]);
                xx = fminf(9.f, fmaxf(-9.f, xx));
                e[j]   = __expf(2.f * xx);
                d[j]   = e[j] + 1.f;
                num[j] = e[j] - 1.f;
            }
            float p01 = d[0] * d[1], p23 = d[2] * d[3];
            float r = rcp_approx(p01 * p23);
            float i01 = r * p23, i23 = r * p01;
            U[0] = num[0] * (i01 * d[1]);
            U[1] = num[1] * (i01 * d[0]);
            U[2] = num[2] * (i23 * d[3]);
            U[3] = num[3] * (i23 * d[2]);

            float p2 = U[0] * c[16 + h4];
#pragma unroll
            for (int j = 1; j < 4; j++) p2 = fmaf(U[j], c[16 + h4 + j], p2);
            float sq = p2 + __shfl_xor_sync(0xffffffffu, p2, 16);

            if (h == 0)
                out[(size_t)(t * BATCH + b) * N_DIM + i] = out_silu(sq);
            vcur = vnext;
        }
    }

    if (writeExtra) {
        float* uf = out + (size_t)M_ROWS * N_DIM + ((size_t)b * N_DIM + i) * 8 + h4;
        *(float4*)uf = make_float4(U[0], U[1], U[2], U[3]);
    }
}

// ============================================================================
// Streams: BOTH non-blocking (legacy stream 0 otherwise serializes with
// blocking streams — this silently serialized all "overlap" in R8-R14).
// Stream 0 is only the fork/join spine.
// ============================================================================
struct AuxStreams {
    cudaStream_t s1, s2;
    cudaEvent_t  fork, evA, evB;
    AuxStreams() {
        cudaStreamCreateWithFlags(&s1, cudaStreamNonBlocking);
        cudaStreamCreateWithFlags(&s2, cudaStreamNonBlocking);
        cudaEventCreateWithFlags(&fork, cudaEventDisableTiming);
        cudaEventCreateWithFlags(&evA,  cudaEventDisableTiming);
        cudaEventCreateWithFlags(&evB,  cudaEventDisableTiming);
    }
};

extern "C" void kernel_launch(void* const* d_in, const int* in_sizes, int n_in,
                              void* d_out, int out_size)
{
    const float* x   = (const float*)d_in[0];
    const float* Wk  = (const float*)d_in[1];
    const float* Wv  = (const float*)d_in[2];
    const float* Wq  = (const float*)d_in[3];
    const float* Wkr = (const float*)d_in[4];
    const float* U0  = (const float*)d_in[5];
    const float* V0  = (const float*)d_in[6];
    float* out = (float*)d_out;

    (void)in_sizes; (void)n_in;

    static AuxStreams aux;

    cudaFuncSetAttribute(gemm_merged,
                         cudaFuncAttributeMaxDynamicSharedMemorySize, 3 * STAGE);

    // Fork from stream 0 (the captured spine)
    cudaEventRecord(aux.fork, 0);
    cudaStreamWaitEvent(aux.s1, aux.fork, 0);
    cudaStreamWaitEvent(aux.s2, aux.fork, 0);

    // Chain A (s1): convert -> merged GEMM (v + norm in one launch)
    convert_kernel<<<18448, 256, 0, aux.s1>>>(x, Wk, Wv);
    gemm_merged<<<dim3(8, 128, 2), 256, 3 * STAGE, aux.s1>>>();
    cudaEventRecord(aux.evA, aux.s1);

    // Chain B (s2): prep -> coef (fp32 pipes; independent of chain A)
    prep_kernel<<<dim3(16, 33), 128, 0, aux.s2>>>(V0, Wk, Wq, Wkr);
    coef_kernel<<<dim3(T_STEPS / 16, BATCH), 256, 0, aux.s2>>>(x);
    cudaEventRecord(aux.evB, aux.s2);

    // Join both chains into stream 0, then scan
    cudaStreamWaitEvent(0, aux.evA, 0);
    cudaStreamWaitEvent(0, aux.evB, 0);
    const int extraElems = 2 * BATCH * N_DIM * R_DIM;
    int writeExtra = (out_size >= M_ROWS * N_DIM + extraElems) ? 1 : 0;
    scan_kernel<<<dim3(N_DIM / 64, BATCH), 128>>>(U0, out, writeExtra);

    if (writeExtra) {
        cudaMemcpyAsync(out + (size_t)M_ROWS * N_DIM + BATCH * N_DIM * R_DIM,
                        V0, (size_t)BATCH * N_DIM * R_DIM * sizeof(float),
                        cudaMemcpyDeviceToDevice, 0);
    }
}

// round 16
// speedup vs baseline: 1.8608x; 1.1997x over previous
#include <cuda_runtime.h>
#include <cuda_fp16.h>
#include <math.h>
#include <stdint.h>

#define T_STEPS 512
#define BATCH   32
#define D_DIM   1024
#define N_DIM   1024
#define R_DIM   8
#define M_ROWS  (T_STEPS*BATCH)   /* 16384 */
#define EPSV    1e-6f
#define KC      64
#define STAGE   32768             /* A-part @0 (16K), B-part @16K */

// ---------------- scratch (static device arrays; no cudaMalloc) ------------
__device__ float g_v[M_ROWS * N_DIM];
__device__ float g_coef[M_ROWS * 24];
__device__ float g_nsq[M_ROWS];
__device__ __half g_Mh[32 * 128 * D_DIM];   // per-b B matrix; rows 24-127 stay 0
__device__ __half g_xh[M_ROWS * D_DIM];
__device__ __half g_wk[D_DIM * D_DIM];
__device__ __half g_wv[D_DIM * D_DIM];

// ---------------- transcendentals -------------------------------------------
__device__ __forceinline__ float out_silu(float s) {
    float xs = fminf(30.f, fmaxf(-30.f, s));
    float e  = __expf(-xs);
    return s * s * __fdividef(1.f, 1.f + e);
}
__device__ __forceinline__ float rcp_approx(float x) {
    float r;
    asm("rcp.approx.f32 %0, %1;" : "=f"(r) : "f"(x));
    return r;
}

// ---------------- PTX helpers ------------------------------------------------
__device__ __forceinline__ uint32_t smem_u32(const void* p) {
    uint32_t a;
    asm("{ .reg .u64 t; cvta.to.shared.u64 t, %1; cvt.u32.u64 %0, t; }"
        : "=r"(a) : "l"(p));
    return a;
}
__device__ __forceinline__ void cp16(uint32_t s, const void* g) {
    asm volatile("cp.async.cg.shared.global [%0], [%1], 16;"
                 :: "r"(s), "l"(g) : "memory");
}
#define LDSM_X4(r0, r1, r2, r3, addr) \
    asm volatile("ldmatrix.sync.aligned.m8n8.x4.shared.b16 {%0,%1,%2,%3}, [%4];" \
        : "=r"(r0), "=r"(r1), "=r"(r2), "=r"(r3) : "r"(addr))
#define MMA_F16(d, a, b0, b1) \
    asm volatile("mma.sync.aligned.m16n8k16.row.col.f32.f16.f16.f32 " \
        "{%0,%1,%2,%3},{%4,%5,%6,%7},{%8,%9},{%0,%1,%2,%3};" \
        : "+f"((d)[0]), "+f"((d)[1]), "+f"((d)[2]), "+f"((d)[3]) \
        : "r"((a)[0]), "r"((a)[1]), "r"((a)[2]), "r"((a)[3]), "r"(b0), "r"(b1))

// ============================================================================
// Convert: x -> fp16, Wk -> fp16, Wv -> fp16; zero g_nsq
// ============================================================================
__global__ __launch_bounds__(256) void convert_kernel(
    const float* __restrict__ x, const float* __restrict__ Wk,
    const float* __restrict__ Wv)
{
    int bid = blockIdx.x;
    const float* src;
    __half* dst;
    size_t idx;
    if (bid < 16384) {
        src = x; dst = g_xh; idx = (size_t)bid * 256 + threadIdx.x;
    } else if (bid < 17408) {
        src = Wk; dst = g_wk; idx = (size_t)(bid - 16384) * 256 + threadIdx.x;
    } else if (bid < 18432) {
        src = Wv; dst = g_wv; idx = (size_t)(bid - 17408) * 256 + threadIdx.x;
    } else {
        size_t z = (size_t)(bid - 18432) * 256 + threadIdx.x;
        ((float4*)g_nsq)[z] = make_float4(0.f, 0.f, 0.f, 0.f);
        return;
    }
    float4 v = ((const float4*)src)[idx];
    ((__half2*)dst)[idx*2]   = __half2{__float2half_rn(v.x), __float2half_rn(v.y)};
    ((__half2*)dst)[idx*2+1] = __half2{__float2half_rn(v.z), __float2half_rn(v.w)};
}

// ============================================================================
// Prep (fp32 compute, fp16 store): per-b M matrices in g_Mh[b][row][d]:
//   rows 0-7:  Mk(b)[j][d] = sum_n V0[b,n,j]*Wk[n,d]
//   rows 8-15: Mr[j][d]    = sum_n Wkr[j,n]*Wk[n,d]   (same for all b)
//   rows 16-23:Mq(b)[j][d] = sum_n V0[b,n,j]*Wq[n,d]
// ============================================================================
__global__ __launch_bounds__(128) void prep_kernel(
    const float* __restrict__ V0, const float* __restrict__ Wk,
    const float* __restrict__ Wq, const float* __restrict__ Wkr)
{
    __shared__ float sP[8][128];
    const int dx  = blockIdx.x;          // 0..15: d-tile (x<8: Wk-side, else Wq)
    const int py  = blockIdx.y;          // 0..31: b;  32: Wkr rows
    const int tid = threadIdx.x;
    const float* W = (dx < 8) ? Wk : Wq;
    const int d = (dx & 7) * 128 + tid;

    float acc[8];
#pragma unroll
    for (int j = 0; j < 8; j++) acc[j] = 0.f;

    for (int n0 = 0; n0 < N_DIM; n0 += 128) {
        __syncthreads();
        for (int idx = tid; idx < 1024; idx += 128) {
            int j = idx >> 7, n = idx & 127;
            float v;
            if (py < 32) v = V0[((size_t)py * N_DIM + n0 + n) * 8 + j];
            else         v = Wkr[(size_t)j * N_DIM + n0 + n];
            sP[j][n] = v;
        }
        __syncthreads();
#pragma unroll 4
        for (int n = 0; n < 128; n++) {
            float w = W[(size_t)(n0 + n) * D_DIM + d];
#pragma unroll
            for (int j = 0; j < 8; j++) acc[j] = fmaf(sP[j][n], w, acc[j]);
        }
    }

    if (py < 32) {
        const int rbase = (dx < 8) ? 0 : 16;
#pragma unroll
        for (int j = 0; j < 8; j++)
            g_Mh[((size_t)py * 128 + rbase + j) * D_DIM + d] =
                __float2half_rn(acc[j]);
    } else {
        if (dx < 8) {   // Mr only exists on the Wk side
#pragma unroll
            for (int j = 0; j < 8; j++) {
                __half hv = __float2half_rn(acc[j]);
                for (int bb = 0; bb < 32; bb++)
                    g_Mh[((size_t)bb * 128 + 8 + j) * D_DIM + d] = hv;
            }
        }
    }
}

// ============================================================================
// Merged single-product fp16 HMMA GEMM, one launch, grid (8,128,2):
//   z=0: xh*Wv -> store g_v ;  z=1: xh*Wk -> row SSQ -> atomicAdd g_nsq.
// 16 K-chunks, 3-stage pipeline (96KB), 2 CTAs/SM.
// ============================================================================
__device__ __forceinline__ void fill_vstage(uint32_t st, int chunk, int tid,
                                            int mt, int nt,
                                            const __half* __restrict__ B0)
{
    const __half* A = g_xh + (size_t)mt * 128 * D_DIM + chunk * KC;
    const __half* B = B0 + (size_t)nt * 128 * D_DIM + chunk * KC;
#pragma unroll
    for (int v = tid; v < 1024; v += 256) {
        int row = v >> 3, c = v & 7;
        uint32_t so = (uint32_t)(row * 128 + ((c * 16) ^ ((row & 7) << 4)));
        size_t go = (size_t)row * D_DIM + c * 8;
        cp16(st + so,         A + go);
        cp16(st + 16384 + so, B + go);
    }
}

__global__ __launch_bounds__(256, 2) void gemm_merged()
{
    constexpr int NCHUNK = 16;
    extern __shared__ char smem[];
    const uint32_t sb = smem_u32(smem);
    const int tid  = threadIdx.x;
    const int lane = tid & 31, wid = tid >> 5;
    const int wm = wid >> 1, wn = wid & 1;
    const int nt = blockIdx.x, mt = blockIdx.y;
    const bool isV = (blockIdx.z == 0);
    const __half* B0 = isV ? g_wv : g_wk;

    const uint32_t aRowOff = (uint32_t)((wm * 32 + (lane & 15)) * 128);
    const uint32_t aSeg    = (uint32_t)((lane >> 4) * 16);
    const uint32_t bRowOff = (uint32_t)((wn * 64 + ((lane >> 4) << 3) + (lane & 7)) * 128);
    const uint32_t bSeg    = (uint32_t)(((lane >> 3) & 1) * 16);
    const uint32_t xorm    = (uint32_t)((lane & 7) << 4);

    float acc[2][8][4];
#pragma unroll
    for (int i = 0; i < 2; i++)
#pragma unroll
        for (int j = 0; j < 8; j++)
#pragma unroll
            for (int e = 0; e < 4; e++) acc[i][j][e] = 0.f;

    fill_vstage(sb, 0, tid, mt, nt, B0);
    asm volatile("cp.async.commit_group;" ::: "memory");
    fill_vstage(sb + STAGE, 1, tid, mt, nt, B0);
    asm volatile("cp.async.commit_group;" ::: "memory");

    for (int c = 0; c < NCHUNK; c++) {
        if (c + 2 < NCHUNK) {
            fill_vstage(sb + ((c + 2) % 3) * STAGE, c + 2, tid, mt, nt, B0);
            asm volatile("cp.async.commit_group;" ::: "memory");
            asm volatile("cp.async.wait_group 2;" ::: "memory");
        } else if (c + 1 < NCHUNK) {
            asm volatile("cp.async.wait_group 1;" ::: "memory");
        } else {
            asm volatile("cp.async.wait_group 0;" ::: "memory");
        }
        __syncthreads();

        const uint32_t sA = sb + (c % 3) * STAGE;
        const uint32_t sB = sA + 16384;

#pragma unroll
        for (int ks = 0; ks < 4; ks++) {
            const uint32_t kb = (uint32_t)(ks * 32);
            uint32_t a[2][4];
#pragma unroll
            for (int i = 0; i < 2; i++) {
                uint32_t ad = sA + i * 2048 + aRowOff + ((kb + aSeg) ^ xorm);
                LDSM_X4(a[i][0], a[i][1], a[i][2], a[i][3], ad);
            }
#pragma unroll
            for (int jp = 0; jp < 4; jp++) {
                uint32_t b0, b1, b2, b3;
                uint32_t bd = sB + jp * 2048 + bRowOff + ((kb + bSeg) ^ xorm);
                LDSM_X4(b0, b1, b2, b3, bd);
#pragma unroll
                for (int i = 0; i < 2; i++) {
                    MMA_F16(acc[i][2*jp],     a[i], b0, b1);
                    MMA_F16(acc[i][2*jp + 1], a[i], b2, b3);
                }
            }
        }
        __syncthreads();
    }

    if (isV) {
#pragma unroll
        for (int i = 0; i < 2; i++) {
            const int r0 = mt * 128 + wm * 32 + i * 16 + (lane >> 2);
#pragma unroll
            for (int j = 0; j < 8; j++) {
                const int col = nt * 128 + wn * 64 + j * 8 + (lane & 3) * 2;
                *(float2*)&g_v[(size_t)r0 * N_DIM + col] =
                    make_float2(acc[i][j][0], acc[i][j][1]);
                *(float2*)&g_v[(size_t)(r0 + 8) * N_DIM + col] =
                    make_float2(acc[i][j][2], acc[i][j][3]);
            }
        }
    } else {
#pragma unroll
        for (int i = 0; i < 2; i++) {
            float s0 = 0.f, s1 = 0.f;
#pragma unroll
            for (int j = 0; j < 8; j++) {
                s0 = fmaf(acc[i][j][0], acc[i][j][0], s0);
                s0 = fmaf(acc[i][j][1], acc[i][j][1], s0);
                s1 = fmaf(acc[i][j][2], acc[i][j][2], s1);
                s1 = fmaf(acc[i][j][3], acc[i][j][3], s1);
            }
            s0 += __shfl_xor_sync(0xffffffffu, s0, 1);
            s0 += __shfl_xor_sync(0xffffffffu, s0, 2);
            s1 += __shfl_xor_sync(0xffffffffu, s1, 1);
            s1 += __shfl_xor_sync(0xffffffffu, s1, 2);
            const int r0 = mt * 128 + wm * 32 + i * 16 + (lane >> 2);
            if ((lane & 3) == 0) {
                atomicAdd(&g_nsq[r0],     s0);
                atomicAdd(&g_nsq[r0 + 8], s1);
            }
        }
    }
}

// ============================================================================
// Coef GEMM: grid (4 mt, 32 b). A = x rows of batch b (stride 32 rows),
// B = g_Mh[b] (128x1024, rows 24-127 zero). Stores cols 0..23 to g_coef.
// ============================================================================
__device__ __forceinline__ void fill_cstage(uint32_t st, int chunk, int tid,
                                            int mt, int b)
{
    const __half* Bm = g_Mh + (size_t)b * 128 * D_DIM + chunk * KC;
#pragma unroll
    for (int v = tid; v < 1024; v += 256) {
        int row = v >> 3, c = v & 7;
        uint32_t so = (uint32_t)(row * 128 + ((c * 16) ^ ((row & 7) << 4)));
        const __half* A = g_xh + ((size_t)(mt * 128 + row) * BATCH + b) * D_DIM
                        + chunk * KC + c * 8;
        cp16(st + so,         A);
        cp16(st + 16384 + so, Bm + (size_t)row * D_DIM + c * 8);
    }
}

__global__ __launch_bounds__(256, 2) void gemm_coef()
{
    constexpr int NCHUNK = 16;
    extern __shared__ char smem[];
    const uint32_t sb = smem_u32(smem);
    const int tid  = threadIdx.x;
    const int lane = tid & 31, wid = tid >> 5;
    const int wm = wid >> 1, wn = wid & 1;
    const int mt = blockIdx.x, b = blockIdx.y;

    const uint32_t aRowOff = (uint32_t)((wm * 32 + (lane & 15)) * 128);
    const uint32_t aSeg    = (uint32_t)((lane >> 4) * 16);
    const uint32_t bRowOff = (uint32_t)((wn * 64 + ((lane >> 4) << 3) + (lane & 7)) * 128);
    const uint32_t bSeg    = (uint32_t)(((lane >> 3) & 1) * 16);
    const uint32_t xorm    = (uint32_t)((lane & 7) << 4);

    float acc[2][8][4];
#pragma unroll
    for (int i = 0; i < 2; i++)
#pragma unroll
        for (int j = 0; j < 8; j++)
#pragma unroll
            for (int e = 0; e < 4; e++) acc[i][j][e] = 0.f;

    fill_cstage(sb, 0, tid, mt, b);
    asm volatile("cp.async.commit_group;" ::: "memory");
    fill_cstage(sb + STAGE, 1, tid, mt, b);
    asm volatile("cp.async.commit_group;" ::: "memory");

    for (int c = 0; c < NCHUNK; c++) {
        if (c + 2 < NCHUNK) {
            fill_cstage(sb + ((c + 2) % 3) * STAGE, c + 2, tid, mt, b);
            asm volatile("cp.async.commit_group;" ::: "memory");
            asm volatile("cp.async.wait_group 2;" ::: "memory");
        } else if (c + 1 < NCHUNK) {
            asm volatile("cp.async.wait_group 1;" ::: "memory");
        } else {
            asm volatile("cp.async.wait_group 0;" ::: "memory");
        }
        __syncthreads();

        const uint32_t sA = sb + (c % 3) * STAGE;
        const uint32_t sB = sA + 16384;

#pragma unroll
        for (int ks = 0; ks < 4; ks++) {
            const uint32_t kb = (uint32_t)(ks * 32);
            uint32_t a[2][4];
#pragma unroll
            for (int i = 0; i < 2; i++) {
                uint32_t ad = sA + i * 2048 + aRowOff + ((kb + aSeg) ^ xorm);
                LDSM_X4(a[i][0], a[i][1], a[i][2], a[i][3], ad);
            }
            // Only wn==0, jp<2 cover the 24 useful cols (0..31)
            if (wn == 0) {
#pragma unroll
                for (int jp = 0; jp < 2; jp++) {
                    uint32_t b0, b1, b2, b3;
                    uint32_t bd = sB + jp * 2048 + bRowOff + ((kb + bSeg) ^ xorm);
                    LDSM_X4(b0, b1, b2, b3, bd);
#pragma unroll
                    for (int i = 0; i < 2; i++) {
                        MMA_F16(acc[i][2*jp],     a[i], b0, b1);
                        MMA_F16(acc[i][2*jp + 1], a[i], b2, b3);
                    }
                }
            }
        }
        __syncthreads();
    }

    if (wn == 0) {
#pragma unroll
        for (int i = 0; i < 2; i++) {
            const int t0 = mt * 128 + wm * 32 + i * 16 + (lane >> 2);
#pragma unroll
            for (int j = 0; j < 3; j++) {      // cols 0..23 only
                const int col = j * 8 + (lane & 3) * 2;
                *(float2*)&g_coef[((size_t)t0 * BATCH + b) * 24 + col] =
                    make_float2(acc[i][j][0], acc[i][j][1]);
                *(float2*)&g_coef[((size_t)(t0 + 8) * BATCH + b) * 24 + col] =
                    make_float2(acc[i][j][2], acc[i][j][3]);
            }
        }
    }
}

// ============================================================================
// Scan: EXACT R13 body (measured-good formulation). Do not touch.
// ============================================================================
__global__ __launch_bounds__(128) void scan_kernel(
    const float* __restrict__ U0, float* __restrict__ out, int writeExtra)
{
    const int CH = 64;
    __shared__ float sc[CH * 24];
    __shared__ float ssc[CH];

    const int b    = blockIdx.y;
    const int tid  = threadIdx.x;
    const int lane = tid & 31, warp = tid >> 5;
    const int h    = lane >> 4;
    const int h4   = h * 4;
    const int i    = blockIdx.x * 64 + warp * 16 + (lane & 15);

    float U[4];
    {
        float4 u = *(const float4*)&U0[((size_t)b * N_DIM + i) * 8 + h4];
        U[0] = u.x; U[1] = u.y; U[2] = u.z; U[3] = u.w;
    }

    float vcur = g_v[(size_t)b * N_DIM + i];

    for (int tc = 0; tc < T_STEPS; tc += CH) {
        __syncthreads();
        if (tid < CH) {
            float ns = g_nsq[(size_t)(tc + tid) * BATCH + b];
            ssc[tid] = __fdividef(1.f, sqrtf(ns) + EPSV);
        }
        for (int idx = tid; idx < CH * 24; idx += 128) {
            int tt = idx / 24;
            sc[idx] = g_coef[(size_t)((tc + tt) * BATCH + b) * 24 + (idx - tt * 24)];
        }
        __syncthreads();

#pragma unroll 2
        for (int tt = 0; tt < CH; tt++) {
            const int t = tc + tt;
            float vnext = (t + 1 < T_STEPS)
                        ? g_v[(size_t)((t + 1) * BATCH + b) * N_DIM + i] : 0.f;
            const float* c = &sc[tt * 24];
            const float s = ssc[tt];

            float part = U[0] * c[h4];
#pragma unroll
            for (int j = 1; j < 4; j++) part = fmaf(U[j], c[h4 + j], part);
            float ret = (part + __shfl_xor_sync(0xffffffffu, part, 16)) * s;
            float dls = (vcur - ret) * s;

            float e[4], d[4], num[4];
#pragma unroll
            for (int j = 0; j < 4; j++) {
                float xx = fmaf(dls, c[8 + h4 + j], U[j]);
                xx = fminf(9.f, fmaxf(-9.f, xx));
                e[j]   = __expf(2.f * xx);
                d[j]   = e[j] + 1.f;
                num[j] = e[j] - 1.f;
            }
            float p01 = d[0] * d[1], p23 = d[2] * d[3];
            float r = rcp_approx(p01 * p23);
            float i01 = r * p23, i23 = r * p01;
            U[0] = num[0] * (i01 * d[1]);
            U[1] = num[1] * (i01 * d[0]);
            U[2] = num[2] * (i23 * d[3]);
            U[3] = num[3] * (i23 * d[2]);

            float p2 = U[0] * c[16 + h4];
#pragma unroll
            for (int j = 1; j < 4; j++) p2 = fmaf(U[j], c[16 + h4 + j], p2);
            float sq = p2 + __shfl_xor_sync(0xffffffffu, p2, 16);

            if (h == 0)
                out[(size_t)(t * BATCH + b) * N_DIM + i] = out_silu(sq);
            vcur = vnext;
        }
    }

    if (writeExtra) {
        float* uf = out + (size_t)M_ROWS * N_DIM + ((size_t)b * N_DIM + i) * 8 + h4;
        *(float4*)uf = make_float4(U[0], U[1], U[2], U[3]);
    }
}

// ============================================================================
// Streams: both non-blocking; stream 0 is only the fork/join spine.
// ============================================================================
struct AuxStreams {
    cudaStream_t s1, s2;
    cudaEvent_t  fork, evConv, evA, evB;
    AuxStreams() {
        cudaStreamCreateWithFlags(&s1, cudaStreamNonBlocking);
        cudaStreamCreateWithFlags(&s2, cudaStreamNonBlocking);
        cudaEventCreateWithFlags(&fork,   cudaEventDisableTiming);
        cudaEventCreateWithFlags(&evConv, cudaEventDisableTiming);
        cudaEventCreateWithFlags(&evA,    cudaEventDisableTiming);
        cudaEventCreateWithFlags(&evB,    cudaEventDisableTiming);
    }
};

extern "C" void kernel_launch(void* const* d_in, const int* in_sizes, int n_in,
                              void* d_out, int out_size)
{
    const float* x   = (const float*)d_in[0];
    const float* Wk  = (const float*)d_in[1];
    const float* Wv  = (const float*)d_in[2];
    const float* Wq  = (const float*)d_in[3];
    const float* Wkr = (const float*)d_in[4];
    const float* U0  = (const float*)d_in[5];
    const float* V0  = (const float*)d_in[6];
    float* out = (float*)d_out;

    (void)in_sizes; (void)n_in;

    static AuxStreams aux;

    cudaFuncSetAttribute(gemm_merged,
                         cudaFuncAttributeMaxDynamicSharedMemorySize, 3 * STAGE);
    cudaFuncSetAttribute(gemm_coef,
                         cudaFuncAttributeMaxDynamicSharedMemorySize, 3 * STAGE);

    // Fork from stream 0 (the captured spine)
    cudaEventRecord(aux.fork, 0);
    cudaStreamWaitEvent(aux.s1, aux.fork, 0);
    cudaStreamWaitEvent(aux.s2, aux.fork, 0);

    // Chain A (s1): convert -> merged GEMM (v + norm)
    convert_kernel<<<18448, 256, 0, aux.s1>>>(x, Wk, Wv);
    cudaEventRecord(aux.evConv, aux.s1);
    gemm_merged<<<dim3(8, 128, 2), 256, 3 * STAGE, aux.s1>>>();
    cudaEventRecord(aux.evA, aux.s1);

    // Chain B (s2): prep -> (wait convert) -> coef GEMM
    prep_kernel<<<dim3(16, 33), 128, 0, aux.s2>>>(V0, Wk, Wq, Wkr);
    cudaStreamWaitEvent(aux.s2, aux.evConv, 0);
    gemm_coef<<<dim3(4, 32), 256, 3 * STAGE, aux.s2>>>();
    cudaEventRecord(aux.evB, aux.s2);

    // Join both chains into stream 0, then scan
    cudaStreamWaitEvent(0, aux.evA, 0);
    cudaStreamWaitEvent(0, aux.evB, 0);
    const int extraElems = 2 * BATCH * N_DIM * R_DIM;
    int writeExtra = (out_size >= M_ROWS * N_DIM + extraElems) ? 1 : 0;
    scan_kernel<<<dim3(N_DIM / 64, BATCH), 128>>>(U0, out, writeExtra);

    if (writeExtra) {
        cudaMemcpyAsync(out + (size_t)M_ROWS * N_DIM + BATCH * N_DIM * R_DIM,
                        V0, (size_t)BATCH * N_DIM * R_DIM * sizeof(float),
                        cudaMemcpyDeviceToDevice, 0);
    }
}

// round 17
// speedup vs baseline: 1.8714x; 1.0057x over previous
#include <cuda_runtime.h>
#include <cuda_fp16.h>
#include <math.h>
#include <stdint.h>

#define T_STEPS 512
#define BATCH   32
#define D_DIM   1024
#define N_DIM   1024
#define R_DIM   8
#define M_ROWS  (T_STEPS*BATCH)   /* 16384 */
#define EPSV    1e-6f
#define KC      64
#define STAGE   32768             /* A-part @0 (16K), B-part @16K */

// ---------------- scratch (static device arrays; no cudaMalloc) ------------
__device__ float g_v[M_ROWS * N_DIM];
__device__ float g_coef[M_ROWS * 24];
__device__ float g_nsq[M_ROWS];
__device__ __half g_Mh[32 * 128 * D_DIM];   // per-b B matrix; rows 24-127 stay 0
__device__ __half g_xh[M_ROWS * D_DIM];
__device__ __half g_wk[D_DIM * D_DIM];
__device__ __half g_wv[D_DIM * D_DIM];

// ---------------- transcendentals -------------------------------------------
__device__ __forceinline__ float out_silu(float s) {
    float xs = fminf(30.f, fmaxf(-30.f, s));
    float e  = __expf(-xs);
    return s * s * __fdividef(1.f, 1.f + e);
}
__device__ __forceinline__ float rcp_approx(float x) {
    float r;
    asm("rcp.approx.f32 %0, %1;" : "=f"(r) : "f"(x));
    return r;
}

// ---------------- PTX helpers ------------------------------------------------
__device__ __forceinline__ uint32_t smem_u32(const void* p) {
    uint32_t a;
    asm("{ .reg .u64 t; cvta.to.shared.u64 t, %1; cvt.u32.u64 %0, t; }"
        : "=r"(a) : "l"(p));
    return a;
}
__device__ __forceinline__ void cp16(uint32_t s, const void* g) {
    asm volatile("cp.async.cg.shared.global [%0], [%1], 16;"
                 :: "r"(s), "l"(g) : "memory");
}
#define LDSM_X4(r0, r1, r2, r3, addr) \
    asm volatile("ldmatrix.sync.aligned.m8n8.x4.shared.b16 {%0,%1,%2,%3}, [%4];" \
        : "=r"(r0), "=r"(r1), "=r"(r2), "=r"(r3) : "r"(addr))
#define MMA_F16(d, a, b0, b1) \
    asm volatile("mma.sync.aligned.m16n8k16.row.col.f32.f16.f16.f32 " \
        "{%0,%1,%2,%3},{%4,%5,%6,%7},{%8,%9},{%0,%1,%2,%3};" \
        : "+f"((d)[0]), "+f"((d)[1]), "+f"((d)[2]), "+f"((d)[3]) \
        : "r"((a)[0]), "r"((a)[1]), "r"((a)[2]), "r"((a)[3]), "r"(b0), "r"(b1))

// ============================================================================
// Convert: x -> fp16, Wk -> fp16, Wv -> fp16; zero g_nsq
// ============================================================================
__global__ __launch_bounds__(256) void convert_kernel(
    const float* __restrict__ x, const float* __restrict__ Wk,
    const float* __restrict__ Wv)
{
    int bid = blockIdx.x;
    const float* src;
    __half* dst;
    size_t idx;
    if (bid < 16384) {
        src = x; dst = g_xh; idx = (size_t)bid * 256 + threadIdx.x;
    } else if (bid < 17408) {
        src = Wk; dst = g_wk; idx = (size_t)(bid - 16384) * 256 + threadIdx.x;
    } else if (bid < 18432) {
        src = Wv; dst = g_wv; idx = (size_t)(bid - 17408) * 256 + threadIdx.x;
    } else {
        size_t z = (size_t)(bid - 18432) * 256 + threadIdx.x;
        ((float4*)g_nsq)[z] = make_float4(0.f, 0.f, 0.f, 0.f);
        return;
    }
    float4 v = ((const float4*)src)[idx];
    ((__half2*)dst)[idx*2]   = __half2{__float2half_rn(v.x), __float2half_rn(v.y)};
    ((__half2*)dst)[idx*2+1] = __half2{__float2half_rn(v.z), __float2half_rn(v.w)};
}

// ============================================================================
// Prep (fp32 compute, fp16 store): per-b M matrices in g_Mh[b][row][d]:
//   rows 0-7: Mk(b); rows 8-15: Mr (same all b); rows 16-23: Mq(b)
// ============================================================================
__global__ __launch_bounds__(128) void prep_kernel(
    const float* __restrict__ V0, const float* __restrict__ Wk,
    const float* __restrict__ Wq, const float* __restrict__ Wkr)
{
    __shared__ float sP[8][128];
    const int dx  = blockIdx.x;          // 0..15: d-tile (x<8: Wk-side, else Wq)
    const int py  = blockIdx.y;          // 0..31: b;  32: Wkr rows
    const int tid = threadIdx.x;
    const float* W = (dx < 8) ? Wk : Wq;
    const int d = (dx & 7) * 128 + tid;

    float acc[8];
#pragma unroll
    for (int j = 0; j < 8; j++) acc[j] = 0.f;

    for (int n0 = 0; n0 < N_DIM; n0 += 128) {
        __syncthreads();
        for (int idx = tid; idx < 1024; idx += 128) {
            int j = idx >> 7, n = idx & 127;
            float v;
            if (py < 32) v = V0[((size_t)py * N_DIM + n0 + n) * 8 + j];
            else         v = Wkr[(size_t)j * N_DIM + n0 + n];
            sP[j][n] = v;
        }
        __syncthreads();
#pragma unroll 4
        for (int n = 0; n < 128; n++) {
            float w = W[(size_t)(n0 + n) * D_DIM + d];
#pragma unroll
            for (int j = 0; j < 8; j++) acc[j] = fmaf(sP[j][n], w, acc[j]);
        }
    }

    if (py < 32) {
        const int rbase = (dx < 8) ? 0 : 16;
#pragma unroll
        for (int j = 0; j < 8; j++)
            g_Mh[((size_t)py * 128 + rbase + j) * D_DIM + d] =
                __float2half_rn(acc[j]);
    } else {
        if (dx < 8) {
#pragma unroll
            for (int j = 0; j < 8; j++) {
                __half hv = __float2half_rn(acc[j]);
                for (int bb = 0; bb < 32; bb++)
                    g_Mh[((size_t)bb * 128 + 8 + j) * D_DIM + d] = hv;
            }
        }
    }
}

// ============================================================================
// Merged single-product fp16 HMMA GEMM, grid (8,128,2):
//   z=0: xh*Wv -> g_v ;  z=1: xh*Wk -> row SSQ -> atomicAdd g_nsq.
// ============================================================================
__device__ __forceinline__ void fill_vstage(uint32_t st, int chunk, int tid,
                                            int mt, int nt,
                                            const __half* __restrict__ B0)
{
    const __half* A = g_xh + (size_t)mt * 128 * D_DIM + chunk * KC;
    const __half* B = B0 + (size_t)nt * 128 * D_DIM + chunk * KC;
#pragma unroll
    for (int v = tid; v < 1024; v += 256) {
        int row = v >> 3, c = v & 7;
        uint32_t so = (uint32_t)(row * 128 + ((c * 16) ^ ((row & 7) << 4)));
        size_t go = (size_t)row * D_DIM + c * 8;
        cp16(st + so,         A + go);
        cp16(st + 16384 + so, B + go);
    }
}

__global__ __launch_bounds__(256, 2) void gemm_merged()
{
    constexpr int NCHUNK = 16;
    extern __shared__ char smem[];
    const uint32_t sb = smem_u32(smem);
    const int tid  = threadIdx.x;
    const int lane = tid & 31, wid = tid >> 5;
    const int wm = wid >> 1, wn = wid & 1;
    const int nt = blockIdx.x, mt = blockIdx.y;
    const bool isV = (blockIdx.z == 0);
    const __half* B0 = isV ? g_wv : g_wk;

    const uint32_t aRowOff = (uint32_t)((wm * 32 + (lane & 15)) * 128);
    const uint32_t aSeg    = (uint32_t)((lane >> 4) * 16);
    const uint32_t bRowOff = (uint32_t)((wn * 64 + ((lane >> 4) << 3) + (lane & 7)) * 128);
    const uint32_t bSeg    = (uint32_t)(((lane >> 3) & 1) * 16);
    const uint32_t xorm    = (uint32_t)((lane & 7) << 4);

    float acc[2][8][4];
#pragma unroll
    for (int i = 0; i < 2; i++)
#pragma unroll
        for (int j = 0; j < 8; j++)
#pragma unroll
            for (int e = 0; e < 4; e++) acc[i][j][e] = 0.f;

    fill_vstage(sb, 0, tid, mt, nt, B0);
    asm volatile("cp.async.commit_group;" ::: "memory");
    fill_vstage(sb + STAGE, 1, tid, mt, nt, B0);
    asm volatile("cp.async.commit_group;" ::: "memory");

    for (int c = 0; c < NCHUNK; c++) {
        if (c + 2 < NCHUNK) {
            fill_vstage(sb + ((c + 2) % 3) * STAGE, c + 2, tid, mt, nt, B0);
            asm volatile("cp.async.commit_group;" ::: "memory");
            asm volatile("cp.async.wait_group 2;" ::: "memory");
        } else if (c + 1 < NCHUNK) {
            asm volatile("cp.async.wait_group 1;" ::: "memory");
        } else {
            asm volatile("cp.async.wait_group 0;" ::: "memory");
        }
        __syncthreads();

        const uint32_t sA = sb + (c % 3) * STAGE;
        const uint32_t sB = sA + 16384;

#pragma unroll
        for (int ks = 0; ks < 4; ks++) {
            const uint32_t kb = (uint32_t)(ks * 32);
            uint32_t a[2][4];
#pragma unroll
            for (int i = 0; i < 2; i++) {
                uint32_t ad = sA + i * 2048 + aRowOff + ((kb + aSeg) ^ xorm);
                LDSM_X4(a[i][0], a[i][1], a[i][2], a[i][3], ad);
            }
#pragma unroll
            for (int jp = 0; jp < 4; jp++) {
                uint32_t b0, b1, b2, b3;
                uint32_t bd = sB + jp * 2048 + bRowOff + ((kb + bSeg) ^ xorm);
                LDSM_X4(b0, b1, b2, b3, bd);
#pragma unroll
                for (int i = 0; i < 2; i++) {
                    MMA_F16(acc[i][2*jp],     a[i], b0, b1);
                    MMA_F16(acc[i][2*jp + 1], a[i], b2, b3);
                }
            }
        }
        __syncthreads();
    }

    if (isV) {
#pragma unroll
        for (int i = 0; i < 2; i++) {
            const int r0 = mt * 128 + wm * 32 + i * 16 + (lane >> 2);
#pragma unroll
            for (int j = 0; j < 8; j++) {
                const int col = nt * 128 + wn * 64 + j * 8 + (lane & 3) * 2;
                *(float2*)&g_v[(size_t)r0 * N_DIM + col] =
                    make_float2(acc[i][j][0], acc[i][j][1]);
                *(float2*)&g_v[(size_t)(r0 + 8) * N_DIM + col] =
                    make_float2(acc[i][j][2], acc[i][j][3]);
            }
        }
    } else {
#pragma unroll
        for (int i = 0; i < 2; i++) {
            float s0 = 0.f, s1 = 0.f;
#pragma unroll
            for (int j = 0; j < 8; j++) {
                s0 = fmaf(acc[i][j][0], acc[i][j][0], s0);
                s0 = fmaf(acc[i][j][1], acc[i][j][1], s0);
                s1 = fmaf(acc[i][j][2], acc[i][j][2], s1);
                s1 = fmaf(acc[i][j][3], acc[i][j][3], s1);
            }
            s0 += __shfl_xor_sync(0xffffffffu, s0, 1);
            s0 += __shfl_xor_sync(0xffffffffu, s0, 2);
            s1 += __shfl_xor_sync(0xffffffffu, s1, 1);
            s1 += __shfl_xor_sync(0xffffffffu, s1, 2);
            const int r0 = mt * 128 + wm * 32 + i * 16 + (lane >> 2);
            if ((lane & 3) == 0) {
                atomicAdd(&g_nsq[r0],     s0);
                atomicAdd(&g_nsq[r0 + 8], s1);
            }
        }
    }
}

// ============================================================================
// Coef GEMM: grid (4 mt, 32 b). A = x rows of batch b, B = g_Mh[b].
// ============================================================================
__device__ __forceinline__ void fill_cstage(uint32_t st, int chunk, int tid,
                                            int mt, int b)
{
    const __half* Bm = g_Mh + (size_t)b * 128 * D_DIM + chunk * KC;
#pragma unroll
    for (int v = tid; v < 1024; v += 256) {
        int row = v >> 3, c = v & 7;
        uint32_t so = (uint32_t)(row * 128 + ((c * 16) ^ ((row & 7) << 4)));
        const __half* A = g_xh + ((size_t)(mt * 128 + row) * BATCH + b) * D_DIM
                        + chunk * KC + c * 8;
        cp16(st + so,         A);
        cp16(st + 16384 + so, Bm + (size_t)row * D_DIM + c * 8);
    }
}

__global__ __launch_bounds__(256, 2) void gemm_coef()
{
    constexpr int NCHUNK = 16;
    extern __shared__ char smem[];
    const uint32_t sb = smem_u32(smem);
    const int tid  = threadIdx.x;
    const int lane = tid & 31, wid = tid >> 5;
    const int wm = wid >> 1, wn = wid & 1;
    const int mt = blockIdx.x, b = blockIdx.y;

    const uint32_t aRowOff = (uint32_t)((wm * 32 + (lane & 15)) * 128);
    const uint32_t aSeg    = (uint32_t)((lane >> 4) * 16);
    const uint32_t bRowOff = (uint32_t)((wn * 64 + ((lane >> 4) << 3) + (lane & 7)) * 128);
    const uint32_t bSeg    = (uint32_t)(((lane >> 3) & 1) * 16);
    const uint32_t xorm    = (uint32_t)((lane & 7) << 4);

    float acc[2][8][4];
#pragma unroll
    for (int i = 0; i < 2; i++)
#pragma unroll
        for (int j = 0; j < 8; j++)
#pragma unroll
            for (int e = 0; e < 4; e++) acc[i][j][e] = 0.f;

    fill_cstage(sb, 0, tid, mt, b);
    asm volatile("cp.async.commit_group;" ::: "memory");
    fill_cstage(sb + STAGE, 1, tid, mt, b);
    asm volatile("cp.async.commit_group;" ::: "memory");

    for (int c = 0; c < NCHUNK; c++) {
        if (c + 2 < NCHUNK) {
            fill_cstage(sb + ((c + 2) % 3) * STAGE, c + 2, tid, mt, b);
            asm volatile("cp.async.commit_group;" ::: "memory");
            asm volatile("cp.async.wait_group 2;" ::: "memory");
        } else if (c + 1 < NCHUNK) {
            asm volatile("cp.async.wait_group 1;" ::: "memory");
        } else {
            asm volatile("cp.async.wait_group 0;" ::: "memory");
        }
        __syncthreads();

        const uint32_t sA = sb + (c % 3) * STAGE;
        const uint32_t sB = sA + 16384;

#pragma unroll
        for (int ks = 0; ks < 4; ks++) {
            const uint32_t kb = (uint32_t)(ks * 32);
            uint32_t a[2][4];
#pragma unroll
            for (int i = 0; i < 2; i++) {
                uint32_t ad = sA + i * 2048 + aRowOff + ((kb + aSeg) ^ xorm);
                LDSM_X4(a[i][0], a[i][1], a[i][2], a[i][3], ad);
            }
            if (wn == 0) {
#pragma unroll
                for (int jp = 0; jp < 2; jp++) {
                    uint32_t b0, b1, b2, b3;
                    uint32_t bd = sB + jp * 2048 + bRowOff + ((kb + bSeg) ^ xorm);
                    LDSM_X4(b0, b1, b2, b3, bd);
#pragma unroll
                    for (int i = 0; i < 2; i++) {
                        MMA_F16(acc[i][2*jp],     a[i], b0, b1);
                        MMA_F16(acc[i][2*jp + 1], a[i], b2, b3);
                    }
                }
            }
        }
        __syncthreads();
    }

    if (wn == 0) {
#pragma unroll
        for (int i = 0; i < 2; i++) {
            const int t0 = mt * 128 + wm * 32 + i * 16 + (lane >> 2);
#pragma unroll
            for (int j = 0; j < 3; j++) {
                const int col = j * 8 + (lane & 3) * 2;
                *(float2*)&g_coef[((size_t)t0 * BATCH + b) * 24 + col] =
                    make_float2(acc[i][j][0], acc[i][j][1]);
                *(float2*)&g_coef[((size_t)(t0 + 8) * BATCH + b) * 24 + col] =
                    make_float2(acc[i][j][2], acc[i][j][3]);
            }
        }
    }
}

// ============================================================================
// Scan: 4 threads per (b,i) row (h=0..3 owns U[2h..2h+1]); same math as R13,
// dot combines via 2-level butterfly (xor 8, xor 16). 128-thr blocks, 32 rows.
// ============================================================================
__global__ __launch_bounds__(128) void scan_kernel(
    const float* __restrict__ U0, float* __restrict__ out, int writeExtra)
{
    const int CH = 64;
    __shared__ float sc[CH * 24];
    __shared__ float ssc[CH];

    const int b    = blockIdx.y;
    const int tid  = threadIdx.x;
    const int lane = tid & 31, warp = tid >> 5;
    const int h    = lane >> 3;          // 0..3
    const int h2   = h * 2;
    const int i    = blockIdx.x * 32 + warp * 8 + (lane & 7);

    float U[2];
    {
        float2 u = *(const float2*)&U0[((size_t)b * N_DIM + i) * 8 + h2];
        U[0] = u.x; U[1] = u.y;
    }

    float vcur = g_v[(size_t)b * N_DIM + i];

    for (int tc = 0; tc < T_STEPS; tc += CH) {
        __syncthreads();
        if (tid < CH) {
            float ns = g_nsq[(size_t)(tc + tid) * BATCH + b];
            ssc[tid] = __fdividef(1.f, sqrtf(ns) + EPSV);
        }
        for (int idx = tid; idx < CH * 24; idx += 128) {
            int tt = idx / 24;
            sc[idx] = g_coef[(size_t)((tc + tt) * BATCH + b) * 24 + (idx - tt * 24)];
        }
        __syncthreads();

#pragma unroll 2
        for (int tt = 0; tt < CH; tt++) {
            const int t = tc + tt;
            float vnext = (t + 1 < T_STEPS)
                        ? g_v[(size_t)((t + 1) * BATCH + b) * N_DIM + i] : 0.f;
            const float* c = &sc[tt * 24];
            const float s = ssc[tt];

            float part = fmaf(U[1], c[h2 + 1], U[0] * c[h2]);
            float p1 = part + __shfl_xor_sync(0xffffffffu, part, 8);
            float ret = (p1 + __shfl_xor_sync(0xffffffffu, p1, 16)) * s;
            float dls = (vcur - ret) * s;

            float e[2], d[2], num[2];
#pragma unroll
            for (int j = 0; j < 2; j++) {
                float xx = fmaf(dls, c[8 + h2 + j], U[j]);
                xx = fminf(9.f, fmaxf(-9.f, xx));
                e[j]   = __expf(2.f * xx);
                d[j]   = e[j] + 1.f;
                num[j] = e[j] - 1.f;
            }
            float r = rcp_approx(d[0] * d[1]);
            U[0] = num[0] * (r * d[1]);
            U[1] = num[1] * (r * d[0]);

            float p2 = fmaf(U[1], c[16 + h2 + 1], U[0] * c[16 + h2]);
            float q1 = p2 + __shfl_xor_sync(0xffffffffu, p2, 8);
            float sq = q1 + __shfl_xor_sync(0xffffffffu, q1, 16);

            if (h == 0)
                out[(size_t)(t * BATCH + b) * N_DIM + i] = out_silu(sq);
            vcur = vnext;
        }
    }

    if (writeExtra) {
        float* uf = out + (size_t)M_ROWS * N_DIM + ((size_t)b * N_DIM + i) * 8 + h2;
        *(float2*)uf = make_float2(U[0], U[1]);
    }
}

// ============================================================================
// Streams: both non-blocking; stream 0 is only the fork/join spine.
// ============================================================================
struct AuxStreams {
    cudaStream_t s1, s2;
    cudaEvent_t  fork, evConv, evA, evB;
    AuxStreams() {
        cudaStreamCreateWithFlags(&s1, cudaStreamNonBlocking);
        cudaStreamCreateWithFlags(&s2, cudaStreamNonBlocking);
        cudaEventCreateWithFlags(&fork,   cudaEventDisableTiming);
        cudaEventCreateWithFlags(&evConv, cudaEventDisableTiming);
        cudaEventCreateWithFlags(&evA,    cudaEventDisableTiming);
        cudaEventCreateWithFlags(&evB,    cudaEventDisableTiming);
    }
};

extern "C" void kernel_launch(void* const* d_in, const int* in_sizes, int n_in,
                              void* d_out, int out_size)
{
    const float* x   = (const float*)d_in[0];
    const float* Wk  = (const float*)d_in[1];
    const float* Wv  = (const float*)d_in[2];
    const float* Wq  = (const float*)d_in[3];
    const float* Wkr = (const float*)d_in[4];
    const float* U0  = (const float*)d_in[5];
    const float* V0  = (const float*)d_in[6];
    float* out = (float*)d_out;

    (void)in_sizes; (void)n_in;

    static AuxStreams aux;

    cudaFuncSetAttribute(gemm_merged,
                         cudaFuncAttributeMaxDynamicSharedMemorySize, 3 * STAGE);
    cudaFuncSetAttribute(gemm_coef,
                         cudaFuncAttributeMaxDynamicSharedMemorySize, 3 * STAGE);

    // Fork from stream 0 (the captured spine)
    cudaEventRecord(aux.fork, 0);
    cudaStreamWaitEvent(aux.s1, aux.fork, 0);
    cudaStreamWaitEvent(aux.s2, aux.fork, 0);

    // Chain A (s1): convert -> merged GEMM (v + norm)
    convert_kernel<<<18448, 256, 0, aux.s1>>>(x, Wk, Wv);
    cudaEventRecord(aux.evConv, aux.s1);
    gemm_merged<<<dim3(8, 128, 2), 256, 3 * STAGE, aux.s1>>>();
    cudaEventRecord(aux.evA, aux.s1);

    // Chain B (s2): prep -> (wait convert) -> coef GEMM
    prep_kernel<<<dim3(16, 33), 128, 0, aux.s2>>>(V0, Wk, Wq, Wkr);
    cudaStreamWaitEvent(aux.s2, aux.evConv, 0);
    gemm_coef<<<dim3(4, 32), 256, 3 * STAGE, aux.s2>>>();
    cudaEventRecord(aux.evB, aux.s2);

    // Join both chains into stream 0, then scan
    cudaStreamWaitEvent(0, aux.evA, 0);
    cudaStreamWaitEvent(0, aux.evB, 0);
    const int extraElems = 2 * BATCH * N_DIM * R_DIM;
    int writeExtra = (out_size >= M_ROWS * N_DIM + extraElems) ? 1 : 0;
    scan_kernel<<<dim3(N_DIM / 32, BATCH), 128>>>(U0, out, writeExtra);

    if (writeExtra) {
        cudaMemcpyAsync(out + (size_t)M_ROWS * N_DIM + BATCH * N_DIM * R_DIM,
                        V0, (size_t)BATCH * N_DIM * R_DIM * sizeof(float),
                        cudaMemcpyDeviceToDevice, 0);
    }
}